// round 1
// baseline (speedup 1.0000x reference)
#include <cuda_runtime.h>
#include <math.h>

#define B_ 4
#define T_ 2048
#define C_ 2048
#define H_ 16
#define D_ 128
#define BT_ (B_*T_)   // 8192

// Scratch (allocation-free rule: __device__ globals)
static __device__ float g_kv[(size_t)BT_ * (2*C_)];   // [8192, 4096]  k | v
static __device__ float g_q [(size_t)BT_ * C_];       // [8192, 2048]
static __device__ float g_attn[(size_t)BT_ * C_];     // [8192, 2048]

// ---------------------------------------------------------------------------
// Generic fp32 GEMM + bias: C[M,N] = A[M,K] @ W[K,N] + bias[N]
// 128x128 block tile, K-tile 8, 256 threads, 8x8 per thread.
// ---------------------------------------------------------------------------
__global__ __launch_bounds__(256)
void sgemm_bias(const float* __restrict__ A, const float* __restrict__ W,
                const float* __restrict__ bias, float* __restrict__ C,
                int M, int N, int K)
{
    __shared__ float As[8][128];
    __shared__ float Bs[8][128];
    const int tid = threadIdx.x;
    const int bx = blockIdx.x * 128;
    const int by = blockIdx.y * 128;
    const int tx = tid & 15;
    const int ty = tid >> 4;

    float acc[8][8];
#pragma unroll
    for (int i = 0; i < 8; ++i)
#pragma unroll
        for (int j = 0; j < 8; ++j) acc[i][j] = 0.f;

    const int arow = tid >> 1, aseg = tid & 1;   // A tile: 128 rows x 2 float4
    const int brow = tid >> 5, bc4  = tid & 31;  // B tile: 8 rows x 32 float4
    const float* Ap = A + (size_t)(by + arow) * K + aseg * 4;
    const float* Bp = W + (size_t)brow * N + bx + bc4 * 4;

    for (int k0 = 0; k0 < K; k0 += 8) {
        float4 a = *(const float4*)(Ap + k0);
        float4 b = *(const float4*)(Bp + (size_t)k0 * N);
        As[aseg*4+0][arow] = a.x;
        As[aseg*4+1][arow] = a.y;
        As[aseg*4+2][arow] = a.z;
        As[aseg*4+3][arow] = a.w;
        *(float4*)(&Bs[brow][bc4*4]) = b;
        __syncthreads();
#pragma unroll
        for (int kk = 0; kk < 8; ++kk) {
            float av[8], bv[8];
            *(float4*)(av)   = *(const float4*)(&As[kk][ty*4]);
            *(float4*)(av+4) = *(const float4*)(&As[kk][64 + ty*4]);
            *(float4*)(bv)   = *(const float4*)(&Bs[kk][tx*4]);
            *(float4*)(bv+4) = *(const float4*)(&Bs[kk][64 + tx*4]);
#pragma unroll
            for (int i = 0; i < 8; ++i)
#pragma unroll
                for (int j = 0; j < 8; ++j)
                    acc[i][j] = fmaf(av[i], bv[j], acc[i][j]);
        }
        __syncthreads();
    }

#pragma unroll
    for (int i = 0; i < 8; ++i) {
        int row = by + ((i < 4) ? (ty*4 + i) : (64 + ty*4 + (i - 4)));
#pragma unroll
        for (int jh = 0; jh < 2; ++jh) {
            int col = bx + jh*64 + tx*4;
            float4 r;
            r.x = acc[i][jh*4+0] + bias[col+0];
            r.y = acc[i][jh*4+1] + bias[col+1];
            r.z = acc[i][jh*4+2] + bias[col+2];
            r.w = acc[i][jh*4+3] + bias[col+3];
            *(float4*)(&C[(size_t)row * N + col]) = r;
        }
    }
}

// ---------------------------------------------------------------------------
// Causal flash attention, fp32. Grid: (T/64, H, B). 256 threads.
// Each 4-lane group owns one query row; each lane holds 32 of 128 O columns.
// Smem: Q tile 64x(128+4 pad) + shared K/V tile 32x(128+4 pad) = 50688 B.
// ---------------------------------------------------------------------------
#define BR 64
#define BC 32
#define PST 132   // padded row stride (floats) -> conflict-free column patterns
#define ATTN_SMEM (((BR + BC) * PST) * (int)sizeof(float))

__global__ __launch_bounds__(256)
void attn_kernel()
{
    extern __shared__ float sm[];
    float* Qs  = sm;                 // [BR][PST]
    float* KVs = sm + BR * PST;      // [BC][PST] (K phase, then V phase)

    const int tid = threadIdx.x;
    const int q0 = blockIdx.x * BR;
    const int h  = blockIdx.y;
    const int b  = blockIdx.z;

    const int r    = tid >> 2;       // query row within tile (0..63)
    const int cq   = tid & 3;        // column-quarter (0..3)
    const int lane = tid & 31;
    const int gbase = lane & ~3;

    // Load Q tile (coalesced), rows = queries, 128 cols of this head
    const float* qsrc = g_q + (size_t)(b*T_ + q0) * C_ + h * D_;
#pragma unroll
    for (int i = 0; i < 8; ++i) {
        int lin = i*256 + tid;
        int rr = lin >> 5;
        int k4 = lin & 31;
        float4 v = *(const float4*)(qsrc + (size_t)rr * C_ + k4*4);
        *(float4*)(&Qs[rr*PST + k4*4]) = v;
    }

    float O[32];
#pragma unroll
    for (int d = 0; d < 32; ++d) O[d] = 0.f;
    float m = -1e30f, l = 0.f;
    const int qi = q0 + r;
    const float scale = 0.088388347648318447f;  // 1/sqrt(128)

    const float* kbase = g_kv + (size_t)(b*T_) * (2*C_) + h * D_;
    const float* vbase = kbase + C_;

    const int ntiles = (q0 + BR) / BC;
    for (int t = 0; t < ntiles; ++t) {
        const int t0 = t * BC;
        __syncthreads();  // prior PV reads done (and Q visible on 1st iter after next sync)
        // Load K tile
#pragma unroll
        for (int i = 0; i < 4; ++i) {
            int lin = i*256 + tid;
            int rr = lin >> 5;
            int k4 = lin & 31;
            float4 v = *(const float4*)(kbase + (size_t)(t0+rr) * (2*C_) + k4*4);
            *(float4*)(&KVs[rr*PST + k4*4]) = v;
        }
        __syncthreads();

        // S tile: this thread computes s[j] = q_row . k_{cq*8+j}
        float s[8];
#pragma unroll
        for (int j = 0; j < 8; ++j) s[j] = 0.f;
#pragma unroll 8
        for (int k4 = 0; k4 < 32; ++k4) {
            float4 qv = *(const float4*)(&Qs[r*PST + k4*4]);
#pragma unroll
            for (int j = 0; j < 8; ++j) {
                float4 kv = *(const float4*)(&KVs[(cq*8+j)*PST + k4*4]);
                s[j] = fmaf(qv.x, kv.x, s[j]);
                s[j] = fmaf(qv.y, kv.y, s[j]);
                s[j] = fmaf(qv.z, kv.z, s[j]);
                s[j] = fmaf(qv.w, kv.w, s[j]);
            }
        }

        // Causal mask + scale, online softmax stats across 4-lane group
        float mt = -1e30f;
#pragma unroll
        for (int j = 0; j < 8; ++j) {
            int kj = t0 + cq*8 + j;
            s[j] = (kj <= qi) ? s[j]*scale : -1e30f;
            mt = fmaxf(mt, s[j]);
        }
        mt = fmaxf(mt, __shfl_xor_sync(0xffffffffu, mt, 1));
        mt = fmaxf(mt, __shfl_xor_sync(0xffffffffu, mt, 2));
        float mnew = fmaxf(m, mt);
        float p[8], ps = 0.f;
#pragma unroll
        for (int j = 0; j < 8; ++j) { p[j] = __expf(s[j] - mnew); ps += p[j]; }
        ps += __shfl_xor_sync(0xffffffffu, ps, 1);
        ps += __shfl_xor_sync(0xffffffffu, ps, 2);
        float alpha = __expf(m - mnew);
        l = l * alpha + ps;
        m = mnew;
#pragma unroll
        for (int d = 0; d < 32; ++d) O[d] *= alpha;

        // Gather the full 32 P values for this row from the 4-lane group
        float pall[32];
#pragma unroll
        for (int src = 0; src < 4; ++src)
#pragma unroll
            for (int j = 0; j < 8; ++j)
                pall[src*8+j] = __shfl_sync(0xffffffffu, p[j], gbase + src, 32);

        __syncthreads();
        // Load V tile (reuse KVs)
#pragma unroll
        for (int i = 0; i < 4; ++i) {
            int lin = i*256 + tid;
            int rr = lin >> 5;
            int k4 = lin & 31;
            float4 v = *(const float4*)(vbase + (size_t)(t0+rr) * (2*C_) + k4*4);
            *(float4*)(&KVs[rr*PST + k4*4]) = v;
        }
        __syncthreads();

        // O += P @ V  (this lane owns d = cq*32 .. cq*32+31)
#pragma unroll 4
        for (int c = 0; c < BC; ++c) {
            float pc = pall[c];
#pragma unroll
            for (int jj = 0; jj < 8; ++jj) {
                float4 v = *(const float4*)(&KVs[c*PST + cq*32 + jj*4]);
                O[jj*4+0] = fmaf(pc, v.x, O[jj*4+0]);
                O[jj*4+1] = fmaf(pc, v.y, O[jj*4+1]);
                O[jj*4+2] = fmaf(pc, v.z, O[jj*4+2]);
                O[jj*4+3] = fmaf(pc, v.w, O[jj*4+3]);
            }
        }
    }

    // Finalize: O /= l, write back to [B,T,C] layout (head-offset columns)
    float inv = 1.f / l;
    float* op = g_attn + (size_t)(b*T_ + qi) * C_ + h*D_ + cq*32;
#pragma unroll
    for (int jj = 0; jj < 8; ++jj) {
        float4 v;
        v.x = O[jj*4+0]*inv;
        v.y = O[jj*4+1]*inv;
        v.z = O[jj*4+2]*inv;
        v.w = O[jj*4+3]*inv;
        *(float4*)(op + jj*4) = v;
    }
}

// ---------------------------------------------------------------------------
extern "C" void kernel_launch(void* const* d_in, const int* in_sizes, int n_in,
                              void* d_out, int out_size)
{
    const float* enc  = (const float*)d_in[0];
    const float* dec  = (const float*)d_in[1];
    const float* W_kv = (const float*)d_in[2];
    const float* b_kv = (const float*)d_in[3];
    const float* W_q  = (const float*)d_in[4];
    const float* b_q  = (const float*)d_in[5];
    const float* W_o  = (const float*)d_in[6];
    const float* b_o  = (const float*)d_in[7];
    float* out = (float*)d_out;

    float *kv_p, *q_p, *attn_p;
    cudaGetSymbolAddress((void**)&kv_p,   g_kv);
    cudaGetSymbolAddress((void**)&q_p,    g_q);
    cudaGetSymbolAddress((void**)&attn_p, g_attn);

    cudaFuncSetAttribute(attn_kernel,
                         cudaFuncAttributeMaxDynamicSharedMemorySize, ATTN_SMEM);

    dim3 blk(256);
    // kv = enc @ W_kv + b_kv   -> [8192, 4096]
    sgemm_bias<<<dim3((2*C_)/128, BT_/128), blk>>>(enc, W_kv, b_kv, kv_p, BT_, 2*C_, C_);
    // q  = dec @ W_q + b_q     -> [8192, 2048]
    sgemm_bias<<<dim3(C_/128, BT_/128), blk>>>(dec, W_q, b_q, q_p, BT_, C_, C_);
    // causal attention -> g_attn [8192, 2048]
    attn_kernel<<<dim3(T_/BR, H_, B_), blk, ATTN_SMEM>>>();
    // out = attn @ W_o + b_o   -> d_out [8192, 2048]
    sgemm_bias<<<dim3(C_/128, BT_/128), blk>>>(attn_p, W_o, b_o, out, BT_, C_, C_);
}

// round 3
// speedup vs baseline: 1.2287x; 1.2287x over previous
#include <cuda_runtime.h>
#include <cuda_bf16.h>
#include <cstdint>
#include <math.h>

#define B_ 4
#define T_ 2048
#define C_ 2048
#define H_ 16
#define D_ 128
#define BT_ (B_*T_)   // 8192

// ---------------------------------------------------------------------------
// Scratch (__device__ globals, allocation-free rule)
// ---------------------------------------------------------------------------
static __device__ float g_kv[(size_t)BT_ * (2*C_)];        // [8192, 4096] fp32
static __device__ float g_q [(size_t)BT_ * C_];            // [8192, 2048] fp32
static __device__ __nv_bfloat16 g_encH[(size_t)BT_ * C_];
static __device__ __nv_bfloat16 g_encL[(size_t)BT_ * C_];
static __device__ __nv_bfloat16 g_decH[(size_t)BT_ * C_];
static __device__ __nv_bfloat16 g_decL[(size_t)BT_ * C_];
static __device__ __nv_bfloat16 g_attnH[(size_t)BT_ * C_];
static __device__ __nv_bfloat16 g_attnL[(size_t)BT_ * C_];
static __device__ __nv_bfloat16 g_WkvTH[(size_t)(2*C_) * C_];  // [4096, 2048]
static __device__ __nv_bfloat16 g_WkvTL[(size_t)(2*C_) * C_];
static __device__ __nv_bfloat16 g_WqTH [(size_t)C_ * C_];      // [2048, 2048]
static __device__ __nv_bfloat16 g_WqTL [(size_t)C_ * C_];
static __device__ __nv_bfloat16 g_WoTH [(size_t)C_ * C_];
static __device__ __nv_bfloat16 g_WoTL [(size_t)C_ * C_];

// ---------------------------------------------------------------------------
// mma.sync helpers (baseline PTX ISA: works on compute_103 virtual arch)
// ---------------------------------------------------------------------------
__device__ __forceinline__ uint32_t smem_u32(const void* p) {
    uint32_t a;
    asm("{ .reg .u64 t; cvta.to.shared.u64 t, %1; cvt.u32.u64 %0, t; }" : "=r"(a) : "l"(p));
    return a;
}
__device__ __forceinline__ void ldsm_x4(uint32_t* r, uint32_t addr) {
    asm volatile("ldmatrix.sync.aligned.x4.m8n8.shared.b16 {%0,%1,%2,%3}, [%4];"
        : "=r"(r[0]), "=r"(r[1]), "=r"(r[2]), "=r"(r[3]) : "r"(addr));
}
__device__ __forceinline__ void mma_bf16(float* c, const uint32_t* a, const uint32_t* b) {
    asm volatile("mma.sync.aligned.m16n8k16.row.col.f32.bf16.bf16.f32 "
        "{%0,%1,%2,%3}, {%4,%5,%6,%7}, {%8,%9}, {%0,%1,%2,%3};"
        : "+f"(c[0]), "+f"(c[1]), "+f"(c[2]), "+f"(c[3])
        : "r"(a[0]), "r"(a[1]), "r"(a[2]), "r"(a[3]), "r"(b[0]), "r"(b[1]));
}

// ---------------------------------------------------------------------------
// Elementwise bf16 hi/lo split: h = bf16(x), l = bf16(x - h)
// ---------------------------------------------------------------------------
__global__ __launch_bounds__(256)
void split_bf16_kernel(const float* __restrict__ in, __nv_bfloat16* __restrict__ outH,
                       __nv_bfloat16* __restrict__ outL, int n4)
{
    int i = blockIdx.x * blockDim.x + threadIdx.x;
    if (i >= n4) return;
    float4 v = ((const float4*)in)[i];
    __nv_bfloat16 h0 = __float2bfloat16(v.x), h1 = __float2bfloat16(v.y);
    __nv_bfloat16 h2 = __float2bfloat16(v.z), h3 = __float2bfloat16(v.w);
    __nv_bfloat162 H0 = __nv_bfloat162(h0, h1), H1 = __nv_bfloat162(h2, h3);
    __nv_bfloat162 L0 = __nv_bfloat162(__float2bfloat16(v.x - __bfloat162float(h0)),
                                       __float2bfloat16(v.y - __bfloat162float(h1)));
    __nv_bfloat162 L1 = __nv_bfloat162(__float2bfloat16(v.z - __bfloat162float(h2)),
                                       __float2bfloat16(v.w - __bfloat162float(h3)));
    ((__nv_bfloat162*)outH)[i*2+0] = H0; ((__nv_bfloat162*)outH)[i*2+1] = H1;
    ((__nv_bfloat162*)outL)[i*2+0] = L0; ((__nv_bfloat162*)outL)[i*2+1] = L1;
}

// ---------------------------------------------------------------------------
// Transpose + split: in [K, N] fp32 -> outH/outL [N, K] bf16
// ---------------------------------------------------------------------------
__global__ __launch_bounds__(256)
void transpose_split_kernel(const float* __restrict__ in, __nv_bfloat16* __restrict__ outH,
                            __nv_bfloat16* __restrict__ outL, int K, int N)
{
    __shared__ float tile[32][33];
    int n0 = blockIdx.x * 32, k0 = blockIdx.y * 32;
    int tx = threadIdx.x, ty = threadIdx.y;   // block (32, 8)
#pragma unroll
    for (int i = 0; i < 4; ++i)
        tile[ty + i*8][tx] = in[(size_t)(k0 + ty + i*8) * N + n0 + tx];
    __syncthreads();
#pragma unroll
    for (int i = 0; i < 4; ++i) {
        float v = tile[tx][ty + i*8];
        __nv_bfloat16 h = __float2bfloat16(v);
        size_t o = (size_t)(n0 + ty + i*8) * K + k0 + tx;
        outH[o] = h;
        outL[o] = __float2bfloat16(v - __bfloat162float(h));
    }
}

// ---------------------------------------------------------------------------
// bf16x3 GEMM via mma.sync: C[M,N] = Ah@BhT + Ah@BlT + Al@BhT + bias
//   A (hi/lo): [M, K] bf16 row-major;  BT (hi/lo): [N, K] bf16 row-major
//   128x128 CTA tile, K-tile 32, 256 threads (8 warps, 4x2 -> 32x64 warp tile)
// ---------------------------------------------------------------------------
#define KT 32
#define APAD 40   // padded row stride (bf16 elems); 80B: conflict-free for ldmatrix

__global__ __launch_bounds__(256, 2)
void gemm_bf16x3(const __nv_bfloat16* __restrict__ Ah, const __nv_bfloat16* __restrict__ Al,
                 const __nv_bfloat16* __restrict__ BTh, const __nv_bfloat16* __restrict__ BTl,
                 const float* __restrict__ bias, float* __restrict__ Cmat,
                 int Ndim, int Kdim)
{
    __shared__ __nv_bfloat16 sAh[128 * APAD];
    __shared__ __nv_bfloat16 sAl[128 * APAD];
    __shared__ __nv_bfloat16 sBh[128 * APAD];
    __shared__ __nv_bfloat16 sBl[128 * APAD];

    const int tid  = threadIdx.x;
    const int wid  = tid >> 5, lane = tid & 31;
    const int wm   = wid >> 1;        // 0..3 : 32-row slab
    const int wn   = wid & 1;         // 0..1 : 64-col slab
    const int nbase = blockIdx.x * 128, mbase = blockIdx.y * 128;

    const uint32_t aAh = smem_u32(sAh), aAl = smem_u32(sAl);
    const uint32_t aBh = smem_u32(sBh), aBl = smem_u32(sBl);

    float acc[2][8][4];
#pragma unroll
    for (int i = 0; i < 2; ++i)
#pragma unroll
        for (int j = 0; j < 8; ++j)
#pragma unroll
            for (int k = 0; k < 4; ++k) acc[i][j][k] = 0.f;

    // ldmatrix lane addressing (elements)
    const int aRowL = (lane & 15), aColL = (lane >> 4) * 8;                 // A: x4 over m16
    const int bRowL = (lane >> 4) * 8 + (lane & 7), bColL = ((lane >> 3) & 1) * 8; // B: x4 over 2 n8-tiles

    // gmem->smem: 512 uint4 per tile; thread handles 2 rows' segments per tile
    const int ldRow = tid >> 2, ldSeg = tid & 3;  // covers rows 0..63; second pass +64

    const int nkt = Kdim / KT;
    for (int kt = 0; kt < nkt; ++kt) {
        const int kofs = kt * KT;
        // ---- load 4 tiles (128 x 32 bf16 each) ----
#pragma unroll
        for (int half = 0; half < 2; ++half) {
            int row = ldRow + half * 64;
            size_t ga = (size_t)(mbase + row) * Kdim + kofs + ldSeg * 8;
            size_t gb = (size_t)(nbase + row) * Kdim + kofs + ldSeg * 8;
            uint32_t so = (uint32_t)(row * APAD + ldSeg * 8) * 2;
            *(uint4*)((char*)sAh + so) = *(const uint4*)(Ah  + ga);
            *(uint4*)((char*)sAl + so) = *(const uint4*)(Al  + ga);
            *(uint4*)((char*)sBh + so) = *(const uint4*)(BTh + gb);
            *(uint4*)((char*)sBl + so) = *(const uint4*)(BTl + gb);
        }
        __syncthreads();

        // ---- compute: 2 k16 steps ----
#pragma unroll
        for (int ks = 0; ks < 2; ++ks) {
            uint32_t ah[2][4], al[2][4];
#pragma unroll
            for (int mt = 0; mt < 2; ++mt) {
                uint32_t off = (uint32_t)((wm*32 + mt*16 + aRowL) * APAD + ks*16 + aColL) * 2;
                ldsm_x4(ah[mt], aAh + off);
                ldsm_x4(al[mt], aAl + off);
            }
#pragma unroll
            for (int np = 0; np < 4; ++np) {
                uint32_t boff = (uint32_t)((wn*64 + np*16 + bRowL) * APAD + ks*16 + bColL) * 2;
                uint32_t bh[4], bl[4];
                ldsm_x4(bh, aBh + boff);
                ldsm_x4(bl, aBl + boff);
#pragma unroll
                for (int mt = 0; mt < 2; ++mt) {
                    mma_bf16(acc[mt][np*2+0], ah[mt], bh);
                    mma_bf16(acc[mt][np*2+1], ah[mt], bh + 2);
                    mma_bf16(acc[mt][np*2+0], ah[mt], bl);
                    mma_bf16(acc[mt][np*2+1], ah[mt], bl + 2);
                    mma_bf16(acc[mt][np*2+0], al[mt], bh);
                    mma_bf16(acc[mt][np*2+1], al[mt], bh + 2);
                }
            }
        }
        __syncthreads();
    }

    // ---- epilogue: acc -> gmem with bias ----
    const int g = lane >> 2, q2 = (lane & 3) * 2;
#pragma unroll
    for (int mt = 0; mt < 2; ++mt) {
        int r0 = mbase + wm*32 + mt*16 + g;
#pragma unroll
        for (int nt = 0; nt < 8; ++nt) {
            int col = nbase + wn*64 + nt*8 + q2;
            float bx = bias[col], by = bias[col+1];
            float2 v0 = { acc[mt][nt][0] + bx, acc[mt][nt][1] + by };
            float2 v1 = { acc[mt][nt][2] + bx, acc[mt][nt][3] + by };
            *(float2*)(Cmat + (size_t)r0 * Ndim + col)       = v0;
            *(float2*)(Cmat + (size_t)(r0+8) * Ndim + col)   = v1;
        }
    }
}

// ---------------------------------------------------------------------------
// Causal flash attention, fp32 in, writes bf16 hi/lo. Grid: (T/64, H, B). 256 thr.
// ---------------------------------------------------------------------------
#define BR 64
#define BC 32
#define PST 132
#define ATTN_SMEM (((BR + BC) * PST) * (int)sizeof(float))

__global__ __launch_bounds__(256)
void attn_kernel(__nv_bfloat16* __restrict__ attnH, __nv_bfloat16* __restrict__ attnL)
{
    extern __shared__ float sm[];
    float* Qs  = sm;
    float* KVs = sm + BR * PST;

    const int tid = threadIdx.x;
    const int q0 = blockIdx.x * BR;
    const int h  = blockIdx.y;
    const int b  = blockIdx.z;

    const int r    = tid >> 2;
    const int cq   = tid & 3;
    const int lane = tid & 31;
    const int gbase = lane & ~3;

    const float* qsrc = g_q + (size_t)(b*T_ + q0) * C_ + h * D_;
#pragma unroll
    for (int i = 0; i < 8; ++i) {
        int lin = i*256 + tid;
        int rr = lin >> 5, k4 = lin & 31;
        *(float4*)(&Qs[rr*PST + k4*4]) = *(const float4*)(qsrc + (size_t)rr * C_ + k4*4);
    }

    float O[32];
#pragma unroll
    for (int d = 0; d < 32; ++d) O[d] = 0.f;
    float m = -1e30f, l = 0.f;
    const int qi = q0 + r;
    const float scale = 0.088388347648318447f;

    const float* kbase = g_kv + (size_t)(b*T_) * (2*C_) + h * D_;
    const float* vbase = kbase + C_;

    const int ntiles = (q0 + BR) / BC;
    for (int t = 0; t < ntiles; ++t) {
        const int t0 = t * BC;
        __syncthreads();
#pragma unroll
        for (int i = 0; i < 4; ++i) {
            int lin = i*256 + tid;
            int rr = lin >> 5, k4 = lin & 31;
            *(float4*)(&KVs[rr*PST + k4*4]) = *(const float4*)(kbase + (size_t)(t0+rr) * (2*C_) + k4*4);
        }
        __syncthreads();

        float s[8];
#pragma unroll
        for (int j = 0; j < 8; ++j) s[j] = 0.f;
#pragma unroll 8
        for (int k4 = 0; k4 < 32; ++k4) {
            float4 qv = *(const float4*)(&Qs[r*PST + k4*4]);
#pragma unroll
            for (int j = 0; j < 8; ++j) {
                float4 kv = *(const float4*)(&KVs[(cq*8+j)*PST + k4*4]);
                s[j] = fmaf(qv.x, kv.x, s[j]);
                s[j] = fmaf(qv.y, kv.y, s[j]);
                s[j] = fmaf(qv.z, kv.z, s[j]);
                s[j] = fmaf(qv.w, kv.w, s[j]);
            }
        }

        float mt = -1e30f;
#pragma unroll
        for (int j = 0; j < 8; ++j) {
            int kj = t0 + cq*8 + j;
            s[j] = (kj <= qi) ? s[j]*scale : -1e30f;
            mt = fmaxf(mt, s[j]);
        }
        mt = fmaxf(mt, __shfl_xor_sync(0xffffffffu, mt, 1));
        mt = fmaxf(mt, __shfl_xor_sync(0xffffffffu, mt, 2));
        float mnew = fmaxf(m, mt);
        float p[8], ps = 0.f;
#pragma unroll
        for (int j = 0; j < 8; ++j) { p[j] = __expf(s[j] - mnew); ps += p[j]; }
        ps += __shfl_xor_sync(0xffffffffu, ps, 1);
        ps += __shfl_xor_sync(0xffffffffu, ps, 2);
        float alpha = __expf(m - mnew);
        l = l * alpha + ps;
        m = mnew;
#pragma unroll
        for (int d = 0; d < 32; ++d) O[d] *= alpha;

        float pall[32];
#pragma unroll
        for (int src = 0; src < 4; ++src)
#pragma unroll
            for (int j = 0; j < 8; ++j)
                pall[src*8+j] = __shfl_sync(0xffffffffu, p[j], gbase + src, 32);

        __syncthreads();
#pragma unroll
        for (int i = 0; i < 4; ++i) {
            int lin = i*256 + tid;
            int rr = lin >> 5, k4 = lin & 31;
            *(float4*)(&KVs[rr*PST + k4*4]) = *(const float4*)(vbase + (size_t)(t0+rr) * (2*C_) + k4*4);
        }
        __syncthreads();

#pragma unroll 4
        for (int c = 0; c < BC; ++c) {
            float pc = pall[c];
#pragma unroll
            for (int jj = 0; jj < 8; ++jj) {
                float4 v = *(const float4*)(&KVs[c*PST + cq*32 + jj*4]);
                O[jj*4+0] = fmaf(pc, v.x, O[jj*4+0]);
                O[jj*4+1] = fmaf(pc, v.y, O[jj*4+1]);
                O[jj*4+2] = fmaf(pc, v.z, O[jj*4+2]);
                O[jj*4+3] = fmaf(pc, v.w, O[jj*4+3]);
            }
        }
    }

    float inv = 1.f / l;
    __nv_bfloat16 hh[32], ll[32];
#pragma unroll
    for (int jj = 0; jj < 32; ++jj) {
        float v = O[jj] * inv;
        __nv_bfloat16 hb = __float2bfloat16(v);
        hh[jj] = hb;
        ll[jj] = __float2bfloat16(v - __bfloat162float(hb));
    }
    size_t base = (size_t)(b*T_ + qi) * C_ + h*D_ + cq*32;
#pragma unroll
    for (int c = 0; c < 4; ++c) {
        *(uint4*)(attnH + base + c*8) = *(uint4*)(&hh[c*8]);
        *(uint4*)(attnL + base + c*8) = *(uint4*)(&ll[c*8]);
    }
}

// ---------------------------------------------------------------------------
extern "C" void kernel_launch(void* const* d_in, const int* in_sizes, int n_in,
                              void* d_out, int out_size)
{
    const float* enc  = (const float*)d_in[0];
    const float* dec  = (const float*)d_in[1];
    const float* W_kv = (const float*)d_in[2];
    const float* b_kv = (const float*)d_in[3];
    const float* W_q  = (const float*)d_in[4];
    const float* b_q  = (const float*)d_in[5];
    const float* W_o  = (const float*)d_in[6];
    const float* b_o  = (const float*)d_in[7];
    float* out = (float*)d_out;

    float *kv_p, *q_p;
    __nv_bfloat16 *encH, *encL, *decH, *decL, *attnH, *attnL;
    __nv_bfloat16 *WkvTH, *WkvTL, *WqTH, *WqTL, *WoTH, *WoTL;
    cudaGetSymbolAddress((void**)&kv_p,  g_kv);
    cudaGetSymbolAddress((void**)&q_p,   g_q);
    cudaGetSymbolAddress((void**)&encH,  g_encH);
    cudaGetSymbolAddress((void**)&encL,  g_encL);
    cudaGetSymbolAddress((void**)&decH,  g_decH);
    cudaGetSymbolAddress((void**)&decL,  g_decL);
    cudaGetSymbolAddress((void**)&attnH, g_attnH);
    cudaGetSymbolAddress((void**)&attnL, g_attnL);
    cudaGetSymbolAddress((void**)&WkvTH, g_WkvTH);
    cudaGetSymbolAddress((void**)&WkvTL, g_WkvTL);
    cudaGetSymbolAddress((void**)&WqTH,  g_WqTH);
    cudaGetSymbolAddress((void**)&WqTL,  g_WqTL);
    cudaGetSymbolAddress((void**)&WoTH,  g_WoTH);
    cudaGetSymbolAddress((void**)&WoTL,  g_WoTL);

    cudaFuncSetAttribute(attn_kernel, cudaFuncAttributeMaxDynamicSharedMemorySize, ATTN_SMEM);

    const int n4 = (BT_ * C_) / 4;
    split_bf16_kernel<<<(n4 + 255) / 256, 256>>>(enc, encH, encL, n4);
    split_bf16_kernel<<<(n4 + 255) / 256, 256>>>(dec, decH, decL, n4);
    transpose_split_kernel<<<dim3((2*C_)/32, C_/32), dim3(32, 8)>>>(W_kv, WkvTH, WkvTL, C_, 2*C_);
    transpose_split_kernel<<<dim3(C_/32, C_/32), dim3(32, 8)>>>(W_q, WqTH, WqTL, C_, C_);
    transpose_split_kernel<<<dim3(C_/32, C_/32), dim3(32, 8)>>>(W_o, WoTH, WoTL, C_, C_);

    // kv = enc @ W_kv + b_kv  -> [8192, 4096]
    gemm_bf16x3<<<dim3((2*C_)/128, BT_/128), 256>>>(encH, encL, WkvTH, WkvTL, b_kv, kv_p, 2*C_, C_);
    // q = dec @ W_q + b_q     -> [8192, 2048]
    gemm_bf16x3<<<dim3(C_/128, BT_/128), 256>>>(decH, decL, WqTH, WqTL, b_q, q_p, C_, C_);
    // attention -> attnH/attnL bf16 hi/lo
    attn_kernel<<<dim3(T_/BR, H_, B_), 256, ATTN_SMEM>>>(attnH, attnL);
    // out = attn @ W_o + b_o  -> d_out
    gemm_bf16x3<<<dim3(C_/128, BT_/128), 256>>>(attnH, attnL, WoTH, WoTL, b_o, out, C_, C_);
}

// round 5
// speedup vs baseline: 7.5372x; 6.1341x over previous
#include <cuda_runtime.h>
#include <cuda_bf16.h>
#include <cstdint>
#include <math.h>

#define B_ 4
#define T_ 2048
#define C_ 2048
#define H_ 16
#define D_ 128
#define BT_ (B_*T_)   // 8192

// ---------------------------------------------------------------------------
// Scratch (__device__ globals, allocation-free rule)
// ---------------------------------------------------------------------------
static __device__ __nv_bfloat16 g_encH[(size_t)BT_ * C_];
static __device__ __nv_bfloat16 g_encL[(size_t)BT_ * C_];
static __device__ __nv_bfloat16 g_decH[(size_t)BT_ * C_];
static __device__ __nv_bfloat16 g_decL[(size_t)BT_ * C_];
static __device__ __nv_bfloat16 g_kvH [(size_t)BT_ * (2*C_)];  // k | v, bf16 hi
static __device__ __nv_bfloat16 g_kvL [(size_t)BT_ * (2*C_)];  // bf16 lo
static __device__ __nv_bfloat16 g_qH  [(size_t)BT_ * C_];
static __device__ __nv_bfloat16 g_qL  [(size_t)BT_ * C_];
static __device__ __nv_bfloat16 g_attnH[(size_t)BT_ * C_];
static __device__ __nv_bfloat16 g_attnL[(size_t)BT_ * C_];
static __device__ __nv_bfloat16 g_WkvTH[(size_t)(2*C_) * C_];
static __device__ __nv_bfloat16 g_WkvTL[(size_t)(2*C_) * C_];
static __device__ __nv_bfloat16 g_WqTH [(size_t)C_ * C_];
static __device__ __nv_bfloat16 g_WqTL [(size_t)C_ * C_];
static __device__ __nv_bfloat16 g_WoTH [(size_t)C_ * C_];
static __device__ __nv_bfloat16 g_WoTL [(size_t)C_ * C_];

// ---------------------------------------------------------------------------
// mma.sync helpers (baseline PTX ISA: works on compute_103 virtual arch)
// ---------------------------------------------------------------------------
__device__ __forceinline__ uint32_t smem_u32(const void* p) {
    uint32_t a;
    asm("{ .reg .u64 t; cvta.to.shared.u64 t, %1; cvt.u32.u64 %0, t; }" : "=r"(a) : "l"(p));
    return a;
}
__device__ __forceinline__ void ldsm_x4(uint32_t* r, uint32_t addr) {
    asm volatile("ldmatrix.sync.aligned.x4.m8n8.shared.b16 {%0,%1,%2,%3}, [%4];"
        : "=r"(r[0]), "=r"(r[1]), "=r"(r[2]), "=r"(r[3]) : "r"(addr));
}
__device__ __forceinline__ void ldsm_x4_t(uint32_t* r, uint32_t addr) {
    asm volatile("ldmatrix.sync.aligned.m8n8.x4.trans.shared.b16 {%0,%1,%2,%3}, [%4];"
        : "=r"(r[0]), "=r"(r[1]), "=r"(r[2]), "=r"(r[3]) : "r"(addr));
}
__device__ __forceinline__ void mma_bf16(float* c, const uint32_t* a, const uint32_t* b) {
    asm volatile("mma.sync.aligned.m16n8k16.row.col.f32.bf16.bf16.f32 "
        "{%0,%1,%2,%3}, {%4,%5,%6,%7}, {%8,%9}, {%0,%1,%2,%3};"
        : "+f"(c[0]), "+f"(c[1]), "+f"(c[2]), "+f"(c[3])
        : "r"(a[0]), "r"(a[1]), "r"(a[2]), "r"(a[3]), "r"(b[0]), "r"(b[1]));
}
// split pair of fp32 -> bf16x2 hi + bf16x2 lo (packed u32, .x = first elem)
__device__ __forceinline__ void split2(float x, float y, uint32_t& h, uint32_t& l) {
    __nv_bfloat162 hb = __floats2bfloat162_rn(x, y);
    float2 hf = __bfloat1622float2(hb);
    __nv_bfloat162 lb = __floats2bfloat162_rn(x - hf.x, y - hf.y);
    h = *(uint32_t*)&hb;
    l = *(uint32_t*)&lb;
}

// ---------------------------------------------------------------------------
// Elementwise bf16 hi/lo split
// ---------------------------------------------------------------------------
__global__ __launch_bounds__(256)
void split_bf16_kernel(const float* __restrict__ in, __nv_bfloat16* __restrict__ outH,
                       __nv_bfloat16* __restrict__ outL, int n4)
{
    int i = blockIdx.x * blockDim.x + threadIdx.x;
    if (i >= n4) return;
    float4 v = ((const float4*)in)[i];
    uint32_t h0, l0, h1, l1;
    split2(v.x, v.y, h0, l0);
    split2(v.z, v.w, h1, l1);
    ((uint32_t*)outH)[i*2+0] = h0; ((uint32_t*)outH)[i*2+1] = h1;
    ((uint32_t*)outL)[i*2+0] = l0; ((uint32_t*)outL)[i*2+1] = l1;
}

// ---------------------------------------------------------------------------
// Transpose + split: in [K, N] fp32 -> outH/outL [N, K] bf16
// ---------------------------------------------------------------------------
__global__ __launch_bounds__(256)
void transpose_split_kernel(const float* __restrict__ in, __nv_bfloat16* __restrict__ outH,
                            __nv_bfloat16* __restrict__ outL, int K, int N)
{
    __shared__ float tile[32][33];
    int n0 = blockIdx.x * 32, k0 = blockIdx.y * 32;
    int tx = threadIdx.x, ty = threadIdx.y;   // block (32, 8)
#pragma unroll
    for (int i = 0; i < 4; ++i)
        tile[ty + i*8][tx] = in[(size_t)(k0 + ty + i*8) * N + n0 + tx];
    __syncthreads();
#pragma unroll
    for (int i = 0; i < 4; ++i) {
        float v = tile[tx][ty + i*8];
        __nv_bfloat16 h = __float2bfloat16(v);
        size_t o = (size_t)(n0 + ty + i*8) * K + k0 + tx;
        outH[o] = h;
        outL[o] = __float2bfloat16(v - __bfloat162float(h));
    }
}

// ---------------------------------------------------------------------------
// bf16x3 GEMM via mma.sync: C = Ah@BhT + Ah@BlT + Al@BhT + bias
//   SPLIT=false: write fp32 to Cf.  SPLIT=true: write bf16 hi/lo to Ch/Cl.
// ---------------------------------------------------------------------------
#define KT 32
#define APAD 40

template <bool SPLIT>
__global__ __launch_bounds__(256, 2)
void gemm_bf16x3(const __nv_bfloat16* __restrict__ Ah, const __nv_bfloat16* __restrict__ Al,
                 const __nv_bfloat16* __restrict__ BTh, const __nv_bfloat16* __restrict__ BTl,
                 const float* __restrict__ bias, float* __restrict__ Cf,
                 __nv_bfloat16* __restrict__ Ch, __nv_bfloat16* __restrict__ Cl,
                 int Ndim, int Kdim)
{
    __shared__ __nv_bfloat16 sAh[128 * APAD];
    __shared__ __nv_bfloat16 sAl[128 * APAD];
    __shared__ __nv_bfloat16 sBh[128 * APAD];
    __shared__ __nv_bfloat16 sBl[128 * APAD];

    const int tid  = threadIdx.x;
    const int wid  = tid >> 5, lane = tid & 31;
    const int wm   = wid >> 1;
    const int wn   = wid & 1;
    const int nbase = blockIdx.x * 128, mbase = blockIdx.y * 128;

    const uint32_t aAh = smem_u32(sAh), aAl = smem_u32(sAl);
    const uint32_t aBh = smem_u32(sBh), aBl = smem_u32(sBl);

    float acc[2][8][4];
#pragma unroll
    for (int i = 0; i < 2; ++i)
#pragma unroll
        for (int j = 0; j < 8; ++j)
#pragma unroll
            for (int k = 0; k < 4; ++k) acc[i][j][k] = 0.f;

    const int aRowL = (lane & 15), aColL = (lane >> 4) * 8;
    const int bRowL = (lane >> 4) * 8 + (lane & 7), bColL = ((lane >> 3) & 1) * 8;
    const int ldRow = tid >> 2, ldSeg = tid & 3;

    const int nkt = Kdim / KT;
    for (int kt = 0; kt < nkt; ++kt) {
        const int kofs = kt * KT;
#pragma unroll
        for (int half = 0; half < 2; ++half) {
            int row = ldRow + half * 64;
            size_t ga = (size_t)(mbase + row) * Kdim + kofs + ldSeg * 8;
            size_t gb = (size_t)(nbase + row) * Kdim + kofs + ldSeg * 8;
            uint32_t so = (uint32_t)(row * APAD + ldSeg * 8) * 2;
            *(uint4*)((char*)sAh + so) = *(const uint4*)(Ah  + ga);
            *(uint4*)((char*)sAl + so) = *(const uint4*)(Al  + ga);
            *(uint4*)((char*)sBh + so) = *(const uint4*)(BTh + gb);
            *(uint4*)((char*)sBl + so) = *(const uint4*)(BTl + gb);
        }
        __syncthreads();

#pragma unroll
        for (int ks = 0; ks < 2; ++ks) {
            uint32_t ah[2][4], al[2][4];
#pragma unroll
            for (int mt = 0; mt < 2; ++mt) {
                uint32_t off = (uint32_t)((wm*32 + mt*16 + aRowL) * APAD + ks*16 + aColL) * 2;
                ldsm_x4(ah[mt], aAh + off);
                ldsm_x4(al[mt], aAl + off);
            }
#pragma unroll
            for (int np = 0; np < 4; ++np) {
                uint32_t boff = (uint32_t)((wn*64 + np*16 + bRowL) * APAD + ks*16 + bColL) * 2;
                uint32_t bh[4], bl[4];
                ldsm_x4(bh, aBh + boff);
                ldsm_x4(bl, aBl + boff);
#pragma unroll
                for (int mt = 0; mt < 2; ++mt) {
                    mma_bf16(acc[mt][np*2+0], ah[mt], bh);
                    mma_bf16(acc[mt][np*2+1], ah[mt], bh + 2);
                    mma_bf16(acc[mt][np*2+0], ah[mt], bl);
                    mma_bf16(acc[mt][np*2+1], ah[mt], bl + 2);
                    mma_bf16(acc[mt][np*2+0], al[mt], bh);
                    mma_bf16(acc[mt][np*2+1], al[mt], bh + 2);
                }
            }
        }
        __syncthreads();
    }

    const int g = lane >> 2, q2 = (lane & 3) * 2;
#pragma unroll
    for (int mt = 0; mt < 2; ++mt) {
        int r0 = mbase + wm*32 + mt*16 + g;
#pragma unroll
        for (int nt = 0; nt < 8; ++nt) {
            int col = nbase + wn*64 + nt*8 + q2;
            float bx = bias[col], by = bias[col+1];
            float v0x = acc[mt][nt][0] + bx, v0y = acc[mt][nt][1] + by;
            float v1x = acc[mt][nt][2] + bx, v1y = acc[mt][nt][3] + by;
            if (SPLIT) {
                uint32_t h0, l0, h1, l1;
                split2(v0x, v0y, h0, l0);
                split2(v1x, v1y, h1, l1);
                *(uint32_t*)(Ch + (size_t)r0 * Ndim + col)     = h0;
                *(uint32_t*)(Cl + (size_t)r0 * Ndim + col)     = l0;
                *(uint32_t*)(Ch + (size_t)(r0+8) * Ndim + col) = h1;
                *(uint32_t*)(Cl + (size_t)(r0+8) * Ndim + col) = l1;
            } else {
                *(float2*)(Cf + (size_t)r0 * Ndim + col)     = make_float2(v0x, v0y);
                *(float2*)(Cf + (size_t)(r0+8) * Ndim + col) = make_float2(v1x, v1y);
            }
        }
    }
}

// ---------------------------------------------------------------------------
// mma.sync causal flash attention, bf16x3 everywhere.
// Grid (T/64, H, B), 128 threads (4 warps). Warp w owns q rows [w*16, w*16+16).
// Smem: Q/K/V hi+lo tiles, 64 x 136 bf16 each (row stride 272 B).
// ---------------------------------------------------------------------------
#define ASTB 272
#define TILE_B (64 * ASTB)          // 17408
#define ATT_SMEM (6 * TILE_B)       // 104448

__global__ __launch_bounds__(128)
void attn_mma(const __nv_bfloat16* __restrict__ qH, const __nv_bfloat16* __restrict__ qL,
              const __nv_bfloat16* __restrict__ kvH, const __nv_bfloat16* __restrict__ kvL,
              __nv_bfloat16* __restrict__ attnH, __nv_bfloat16* __restrict__ attnL)
{
    extern __shared__ char smem[];
    const uint32_t sb = smem_u32(smem);
    const uint32_t sQH = sb, sKH = sb + 2*TILE_B, sVH = sb + 4*TILE_B;

    const int tid = threadIdx.x, w = tid >> 5, lane = tid & 31;
    const int q0 = blockIdx.x * 64, h = blockIdx.y, b = blockIdx.z;
    const int g = lane >> 2, qq = lane & 3;

    // ---- load Q hi/lo tile ----
#pragma unroll
    for (int i = 0; i < 8; ++i) {
        int lin = i*128 + tid;
        int r = lin >> 4, seg = lin & 15;
        size_t go = (size_t)(b*T_ + q0 + r) * C_ + h*D_ + seg*8;
        uint32_t so = (uint32_t)(r * ASTB + seg * 16);
        *(uint4*)(smem + so)          = *(const uint4*)(qH + go);
        *(uint4*)(smem + TILE_B + so) = *(const uint4*)(qL + go);
    }

    float O[16][4];
#pragma unroll
    for (int i = 0; i < 16; ++i)
#pragma unroll
        for (int j = 0; j < 4; ++j) O[i][j] = 0.f;
    float mA = -1e30f, mB = -1e30f, lA = 0.f, lB = 0.f;
    const float scale = 0.088388347648318447f;   // 1/sqrt(128)

    // fragment lane addressing
    const uint32_t qAddr = sQH + (uint32_t)((w*16 + (lane & 15)) * ASTB + ((lane >> 4) * 8) * 2);
    const int kRowL = (lane >> 4) * 8 + (lane & 7);
    const int kColL = ((lane >> 3) & 1) * 8;
    const int vRowL = ((lane >> 3) & 1) * 8 + (lane & 7);
    const int vColL = (lane >> 4) * 8;

    const int ntl = q0 / 64 + 1;
    for (int t = 0; t < ntl; ++t) {
        const int t0 = t * 64;
        // ---- load K/V hi/lo tiles ----
#pragma unroll
        for (int i = 0; i < 8; ++i) {
            int lin = i*128 + tid;
            int r = lin >> 4, seg = lin & 15;
            size_t ko = (size_t)(b*T_ + t0 + r) * (2*C_) + h*D_ + seg*8;
            uint32_t so = (uint32_t)(r * ASTB + seg * 16);
            *(uint4*)(smem + 2*TILE_B + so) = *(const uint4*)(kvH + ko);
            *(uint4*)(smem + 3*TILE_B + so) = *(const uint4*)(kvL + ko);
            *(uint4*)(smem + 4*TILE_B + so) = *(const uint4*)(kvH + ko + C_);
            *(uint4*)(smem + 5*TILE_B + so) = *(const uint4*)(kvL + ko + C_);
        }
        __syncthreads();

        // ---- S = Q K^T (bf16x3) ----
        float S[8][4];
#pragma unroll
        for (int i = 0; i < 8; ++i)
#pragma unroll
            for (int j = 0; j < 4; ++j) S[i][j] = 0.f;
#pragma unroll
        for (int ks = 0; ks < 8; ++ks) {
            uint32_t qh[4], ql[4];
            ldsm_x4(qh, qAddr + ks*32);
            ldsm_x4(ql, qAddr + TILE_B + ks*32);
#pragma unroll
            for (int grp = 0; grp < 4; ++grp) {
                uint32_t ka = sKH + (uint32_t)((grp*16 + kRowL) * ASTB + (ks*16 + kColL) * 2);
                uint32_t kh[4], kl[4];
                ldsm_x4(kh, ka);
                ldsm_x4(kl, ka + TILE_B);
                mma_bf16(S[grp*2+0], qh, kh);
                mma_bf16(S[grp*2+1], qh, kh + 2);
                mma_bf16(S[grp*2+0], qh, kl);
                mma_bf16(S[grp*2+1], qh, kl + 2);
                mma_bf16(S[grp*2+0], ql, kh);
                mma_bf16(S[grp*2+1], ql, kh + 2);
            }
        }

        // ---- scale + causal mask + online softmax ----
        const int rA = q0 + w*16 + g, rB = rA + 8;
        const bool diag = (t == ntl - 1);
        float mtA = -1e30f, mtB = -1e30f;
#pragma unroll
        for (int nt = 0; nt < 8; ++nt) {
#pragma unroll
            for (int c = 0; c < 4; ++c) S[nt][c] *= scale;
            if (diag) {
                int kj = t0 + nt*8 + qq*2;
                if (kj   > rA) S[nt][0] = -1e30f;
                if (kj+1 > rA) S[nt][1] = -1e30f;
                if (kj   > rB) S[nt][2] = -1e30f;
                if (kj+1 > rB) S[nt][3] = -1e30f;
            }
            mtA = fmaxf(mtA, fmaxf(S[nt][0], S[nt][1]));
            mtB = fmaxf(mtB, fmaxf(S[nt][2], S[nt][3]));
        }
        mtA = fmaxf(mtA, __shfl_xor_sync(0xffffffffu, mtA, 1));
        mtA = fmaxf(mtA, __shfl_xor_sync(0xffffffffu, mtA, 2));
        mtB = fmaxf(mtB, __shfl_xor_sync(0xffffffffu, mtB, 1));
        mtB = fmaxf(mtB, __shfl_xor_sync(0xffffffffu, mtB, 2));
        float nmA = fmaxf(mA, mtA), nmB = fmaxf(mB, mtB);
        float aA = __expf(mA - nmA), aB = __expf(mB - nmB);
        float psA = 0.f, psB = 0.f;
#pragma unroll
        for (int nt = 0; nt < 8; ++nt) {
            S[nt][0] = __expf(S[nt][0] - nmA);
            S[nt][1] = __expf(S[nt][1] - nmA);
            S[nt][2] = __expf(S[nt][2] - nmB);
            S[nt][3] = __expf(S[nt][3] - nmB);
            psA += S[nt][0] + S[nt][1];
            psB += S[nt][2] + S[nt][3];
        }
        psA += __shfl_xor_sync(0xffffffffu, psA, 1);
        psA += __shfl_xor_sync(0xffffffffu, psA, 2);
        psB += __shfl_xor_sync(0xffffffffu, psB, 1);
        psB += __shfl_xor_sync(0xffffffffu, psB, 2);
        lA = lA * aA + psA;  mA = nmA;
        lB = lB * aB + psB;  mB = nmB;
#pragma unroll
        for (int nt = 0; nt < 16; ++nt) {
            O[nt][0] *= aA; O[nt][1] *= aA;
            O[nt][2] *= aB; O[nt][3] *= aB;
        }

        // ---- O += P V (bf16x3); P from S accum regs (A-frag layout) ----
#pragma unroll
        for (int ks = 0; ks < 4; ++ks) {
            uint32_t ah[4], al[4];
            split2(S[2*ks][0],   S[2*ks][1],   ah[0], al[0]);
            split2(S[2*ks][2],   S[2*ks][3],   ah[1], al[1]);
            split2(S[2*ks+1][0], S[2*ks+1][1], ah[2], al[2]);
            split2(S[2*ks+1][2], S[2*ks+1][3], ah[3], al[3]);
#pragma unroll
            for (int dg = 0; dg < 8; ++dg) {
                uint32_t va = sVH + (uint32_t)((ks*16 + vRowL) * ASTB + (dg*16 + vColL) * 2);
                uint32_t vh[4], vl[4];
                ldsm_x4_t(vh, va);
                ldsm_x4_t(vl, va + TILE_B);
                mma_bf16(O[dg*2+0], ah, vh);
                mma_bf16(O[dg*2+1], ah, vh + 2);
                mma_bf16(O[dg*2+0], ah, vl);
                mma_bf16(O[dg*2+1], ah, vl + 2);
                mma_bf16(O[dg*2+0], al, vh);
                mma_bf16(O[dg*2+1], al, vh + 2);
            }
        }
        __syncthreads();
    }

    // ---- finalize: O /= l, write bf16 hi/lo ----
    const float iA = 1.f / lA, iB = 1.f / lB;
    const int rA = q0 + w*16 + g, rB = rA + 8;
    size_t baseA = (size_t)(b*T_ + rA) * C_ + h*D_ + qq*2;
    size_t baseB = (size_t)(b*T_ + rB) * C_ + h*D_ + qq*2;
#pragma unroll
    for (int nt = 0; nt < 16; ++nt) {
        uint32_t hA, lA_, hB, lB_;
        split2(O[nt][0]*iA, O[nt][1]*iA, hA, lA_);
        split2(O[nt][2]*iB, O[nt][3]*iB, hB, lB_);
        *(uint32_t*)(attnH + baseA + nt*8) = hA;
        *(uint32_t*)(attnL + baseA + nt*8) = lA_;
        *(uint32_t*)(attnH + baseB + nt*8) = hB;
        *(uint32_t*)(attnL + baseB + nt*8) = lB_;
    }
}

// ---------------------------------------------------------------------------
extern "C" void kernel_launch(void* const* d_in, const int* in_sizes, int n_in,
                              void* d_out, int out_size)
{
    const float* enc  = (const float*)d_in[0];
    const float* dec  = (const float*)d_in[1];
    const float* W_kv = (const float*)d_in[2];
    const float* b_kv = (const float*)d_in[3];
    const float* W_q  = (const float*)d_in[4];
    const float* b_q  = (const float*)d_in[5];
    const float* W_o  = (const float*)d_in[6];
    const float* b_o  = (const float*)d_in[7];
    float* out = (float*)d_out;

    __nv_bfloat16 *encH, *encL, *decH, *decL, *kvH, *kvL, *qH, *qL, *attnH, *attnL;
    __nv_bfloat16 *WkvTH, *WkvTL, *WqTH, *WqTL, *WoTH, *WoTL;
    cudaGetSymbolAddress((void**)&encH,  g_encH);
    cudaGetSymbolAddress((void**)&encL,  g_encL);
    cudaGetSymbolAddress((void**)&decH,  g_decH);
    cudaGetSymbolAddress((void**)&decL,  g_decL);
    cudaGetSymbolAddress((void**)&kvH,   g_kvH);
    cudaGetSymbolAddress((void**)&kvL,   g_kvL);
    cudaGetSymbolAddress((void**)&qH,    g_qH);
    cudaGetSymbolAddress((void**)&qL,    g_qL);
    cudaGetSymbolAddress((void**)&attnH, g_attnH);
    cudaGetSymbolAddress((void**)&attnL, g_attnL);
    cudaGetSymbolAddress((void**)&WkvTH, g_WkvTH);
    cudaGetSymbolAddress((void**)&WkvTL, g_WkvTL);
    cudaGetSymbolAddress((void**)&WqTH,  g_WqTH);
    cudaGetSymbolAddress((void**)&WqTL,  g_WqTL);
    cudaGetSymbolAddress((void**)&WoTH,  g_WoTH);
    cudaGetSymbolAddress((void**)&WoTL,  g_WoTL);

    cudaFuncSetAttribute(attn_mma, cudaFuncAttributeMaxDynamicSharedMemorySize, ATT_SMEM);

    const int n4 = (BT_ * C_) / 4;
    // launch order chosen so gemm (kv) sits at launch index 3 for the ncu capture
    split_bf16_kernel<<<(n4 + 255) / 256, 256>>>(enc, encH, encL, n4);                       // 0
    split_bf16_kernel<<<(n4 + 255) / 256, 256>>>(dec, decH, decL, n4);                       // 1
    transpose_split_kernel<<<dim3((2*C_)/32, C_/32), dim3(32, 8)>>>(W_kv, WkvTH, WkvTL, C_, 2*C_); // 2
    gemm_bf16x3<true><<<dim3((2*C_)/128, BT_/128), 256>>>(encH, encL, WkvTH, WkvTL, b_kv,
                                                          nullptr, kvH, kvL, 2*C_, C_);      // 3
    transpose_split_kernel<<<dim3(C_/32, C_/32), dim3(32, 8)>>>(W_q, WqTH, WqTL, C_, C_);    // 4
    gemm_bf16x3<true><<<dim3(C_/128, BT_/128), 256>>>(decH, decL, WqTH, WqTL, b_q,
                                                      nullptr, qH, qL, C_, C_);              // 5
    attn_mma<<<dim3(T_/64, H_, B_), 128, ATT_SMEM>>>(qH, qL, kvH, kvL, attnH, attnL);        // 6
    transpose_split_kernel<<<dim3(C_/32, C_/32), dim3(32, 8)>>>(W_o, WoTH, WoTL, C_, C_);    // 7
    gemm_bf16x3<false><<<dim3(C_/128, BT_/128), 256>>>(attnH, attnL, WoTH, WoTL, b_o,
                                                       out, nullptr, nullptr, C_, C_);       // 8
}

// round 7
// speedup vs baseline: 8.0965x; 1.0742x over previous
#include <cuda_runtime.h>
#include <cuda_bf16.h>
#include <cstdint>
#include <math.h>

#define B_ 4
#define T_ 2048
#define C_ 2048
#define H_ 16
#define D_ 128
#define BT_ (B_*T_)   // 8192

// ---------------------------------------------------------------------------
// Scratch (__device__ globals, allocation-free rule)
// ---------------------------------------------------------------------------
static __device__ __nv_bfloat16 g_encH[(size_t)BT_ * C_];
static __device__ __nv_bfloat16 g_encL[(size_t)BT_ * C_];
static __device__ __nv_bfloat16 g_decH[(size_t)BT_ * C_];
static __device__ __nv_bfloat16 g_decL[(size_t)BT_ * C_];
static __device__ __nv_bfloat16 g_kvH [(size_t)BT_ * (2*C_)];
static __device__ __nv_bfloat16 g_kvL [(size_t)BT_ * (2*C_)];
static __device__ __nv_bfloat16 g_qH  [(size_t)BT_ * C_];
static __device__ __nv_bfloat16 g_qL  [(size_t)BT_ * C_];
static __device__ __nv_bfloat16 g_attnH[(size_t)BT_ * C_];
static __device__ __nv_bfloat16 g_attnL[(size_t)BT_ * C_];
static __device__ __nv_bfloat16 g_WkvTH[(size_t)(2*C_) * C_];
static __device__ __nv_bfloat16 g_WkvTL[(size_t)(2*C_) * C_];
static __device__ __nv_bfloat16 g_WqTH [(size_t)C_ * C_];
static __device__ __nv_bfloat16 g_WqTL [(size_t)C_ * C_];
static __device__ __nv_bfloat16 g_WoTH [(size_t)C_ * C_];
static __device__ __nv_bfloat16 g_WoTL [(size_t)C_ * C_];

// ---------------------------------------------------------------------------
// PTX helpers (baseline ISA only — compute_103-safe)
// ---------------------------------------------------------------------------
__device__ __forceinline__ uint32_t smem_u32(const void* p) {
    uint32_t a;
    asm("{ .reg .u64 t; cvta.to.shared.u64 t, %1; cvt.u32.u64 %0, t; }" : "=r"(a) : "l"(p));
    return a;
}
__device__ __forceinline__ void ldsm_x4(uint32_t* r, uint32_t addr) {
    asm volatile("ldmatrix.sync.aligned.x4.m8n8.shared.b16 {%0,%1,%2,%3}, [%4];"
        : "=r"(r[0]), "=r"(r[1]), "=r"(r[2]), "=r"(r[3]) : "r"(addr));
}
__device__ __forceinline__ void ldsm_x4_t(uint32_t* r, uint32_t addr) {
    asm volatile("ldmatrix.sync.aligned.m8n8.x4.trans.shared.b16 {%0,%1,%2,%3}, [%4];"
        : "=r"(r[0]), "=r"(r[1]), "=r"(r[2]), "=r"(r[3]) : "r"(addr));
}
__device__ __forceinline__ void mma_bf16(float* c, const uint32_t* a, const uint32_t* b) {
    asm volatile("mma.sync.aligned.m16n8k16.row.col.f32.bf16.bf16.f32 "
        "{%0,%1,%2,%3}, {%4,%5,%6,%7}, {%8,%9}, {%0,%1,%2,%3};"
        : "+f"(c[0]), "+f"(c[1]), "+f"(c[2]), "+f"(c[3])
        : "r"(a[0]), "r"(a[1]), "r"(a[2]), "r"(a[3]), "r"(b[0]), "r"(b[1]));
}
#define CP16(dst, src) \
    asm volatile("cp.async.cg.shared.global [%0], [%1], 16;" :: "r"(dst), "l"(src))
#define CP_COMMIT() asm volatile("cp.async.commit_group;" ::: "memory")
#define CP_WAIT0()  asm volatile("cp.async.wait_group 0;" ::: "memory")
#define CP_WAIT1()  asm volatile("cp.async.wait_group 1;" ::: "memory")

__device__ __forceinline__ void split2(float x, float y, uint32_t& h, uint32_t& l) {
    __nv_bfloat162 hb = __floats2bfloat162_rn(x, y);
    float2 hf = __bfloat1622float2(hb);
    __nv_bfloat162 lb = __floats2bfloat162_rn(x - hf.x, y - hf.y);
    h = *(uint32_t*)&hb;
    l = *(uint32_t*)&lb;
}

// ---------------------------------------------------------------------------
// Elementwise bf16 hi/lo split
// ---------------------------------------------------------------------------
__global__ __launch_bounds__(256)
void split_bf16_kernel(const float* __restrict__ in, __nv_bfloat16* __restrict__ outH,
                       __nv_bfloat16* __restrict__ outL, int n4)
{
    int i = blockIdx.x * blockDim.x + threadIdx.x;
    if (i >= n4) return;
    float4 v = ((const float4*)in)[i];
    uint32_t h0, l0, h1, l1;
    split2(v.x, v.y, h0, l0);
    split2(v.z, v.w, h1, l1);
    ((uint32_t*)outH)[i*2+0] = h0; ((uint32_t*)outH)[i*2+1] = h1;
    ((uint32_t*)outL)[i*2+0] = l0; ((uint32_t*)outL)[i*2+1] = l1;
}

// ---------------------------------------------------------------------------
// Transpose + split: in [K, N] fp32 -> outH/outL [N, K] bf16
// ---------------------------------------------------------------------------
__global__ __launch_bounds__(256)
void transpose_split_kernel(const float* __restrict__ in, __nv_bfloat16* __restrict__ outH,
                            __nv_bfloat16* __restrict__ outL, int K, int N)
{
    __shared__ float tile[32][33];
    int n0 = blockIdx.x * 32, k0 = blockIdx.y * 32;
    int tx = threadIdx.x, ty = threadIdx.y;
#pragma unroll
    for (int i = 0; i < 4; ++i)
        tile[ty + i*8][tx] = in[(size_t)(k0 + ty + i*8) * N + n0 + tx];
    __syncthreads();
#pragma unroll
    for (int i = 0; i < 4; ++i) {
        float v = tile[tx][ty + i*8];
        __nv_bfloat16 h = __float2bfloat16(v);
        size_t o = (size_t)(n0 + ty + i*8) * K + k0 + tx;
        outH[o] = h;
        outL[o] = __float2bfloat16(v - __bfloat162float(h));
    }
}

// ---------------------------------------------------------------------------
// bf16x3 GEMM, cp.async 2-stage pipeline.
//   C = Ah@BhT + (Ah@Bl + Al@Bh)T + bias;  SPLIT picks fp32 vs bf16-hi/lo out.
// ---------------------------------------------------------------------------
#define KT 32
#define APAD 40
#define GT_BYTES (128 * APAD * 2)     // 10240 B per tile buffer
#define GSTAGE   (4 * GT_BYTES)       // 40960 B per stage
#define GEMM_SMEM (2 * GSTAGE)        // 81920 B

template <bool SPLIT>
__global__ __launch_bounds__(256, 2)
void gemm_bf16x3(const __nv_bfloat16* __restrict__ Ah, const __nv_bfloat16* __restrict__ Al,
                 const __nv_bfloat16* __restrict__ BTh, const __nv_bfloat16* __restrict__ BTl,
                 const float* __restrict__ bias, float* __restrict__ Cf,
                 __nv_bfloat16* __restrict__ Ch, __nv_bfloat16* __restrict__ Cl,
                 int Ndim, int Kdim)
{
    extern __shared__ char gsm[];
    const uint32_t sb = smem_u32(gsm);

    const int tid  = threadIdx.x;
    const int wid  = tid >> 5, lane = tid & 31;
    const int wm   = wid >> 1;
    const int wn   = wid & 1;
    const int nbase = blockIdx.x * 128, mbase = blockIdx.y * 128;

    float acc[2][8][4];
#pragma unroll
    for (int i = 0; i < 2; ++i)
#pragma unroll
        for (int j = 0; j < 8; ++j)
#pragma unroll
            for (int k = 0; k < 4; ++k) acc[i][j][k] = 0.f;

    const int aRowL = (lane & 15), aColL = (lane >> 4) * 8;
    const int bRowL = (lane >> 4) * 8 + (lane & 7), bColL = ((lane >> 3) & 1) * 8;
    const int ldRow = tid >> 2, ldSeg = tid & 3;

    const int nkt = Kdim / KT;

    // stage loader: 8 cp.async of 16B per thread
    auto load_stage = [&](int kt, int s) {
        const int kofs = kt * KT;
        const uint32_t st = sb + s * GSTAGE;
#pragma unroll
        for (int half = 0; half < 2; ++half) {
            int row = ldRow + half * 64;
            size_t ga = (size_t)(mbase + row) * Kdim + kofs + ldSeg * 8;
            size_t gb = (size_t)(nbase + row) * Kdim + kofs + ldSeg * 8;
            uint32_t so = (uint32_t)(row * APAD + ldSeg * 8) * 2;
            CP16(st + 0*GT_BYTES + so, Ah  + ga);
            CP16(st + 1*GT_BYTES + so, Al  + ga);
            CP16(st + 2*GT_BYTES + so, BTh + gb);
            CP16(st + 3*GT_BYTES + so, BTl + gb);
        }
        CP_COMMIT();
    };

    load_stage(0, 0);

    for (int kt = 0; kt < nkt; ++kt) {
        if (kt + 1 < nkt) {
            load_stage(kt + 1, (kt + 1) & 1);
            CP_WAIT1();
        } else {
            CP_WAIT0();
        }
        __syncthreads();

        const uint32_t st = sb + (kt & 1) * GSTAGE;
        const uint32_t aAh = st, aAl = st + GT_BYTES;
        const uint32_t aBh = st + 2*GT_BYTES, aBl = st + 3*GT_BYTES;

#pragma unroll
        for (int ks = 0; ks < 2; ++ks) {
            uint32_t ah[2][4], al[2][4];
#pragma unroll
            for (int mt = 0; mt < 2; ++mt) {
                uint32_t off = (uint32_t)((wm*32 + mt*16 + aRowL) * APAD + ks*16 + aColL) * 2;
                ldsm_x4(ah[mt], aAh + off);
                ldsm_x4(al[mt], aAl + off);
            }
#pragma unroll
            for (int np = 0; np < 4; ++np) {
                uint32_t boff = (uint32_t)((wn*64 + np*16 + bRowL) * APAD + ks*16 + bColL) * 2;
                uint32_t bh[4], bl[4];
                ldsm_x4(bh, aBh + boff);
                ldsm_x4(bl, aBl + boff);
#pragma unroll
                for (int mt = 0; mt < 2; ++mt) {
                    mma_bf16(acc[mt][np*2+0], ah[mt], bh);
                    mma_bf16(acc[mt][np*2+1], ah[mt], bh + 2);
                    mma_bf16(acc[mt][np*2+0], ah[mt], bl);
                    mma_bf16(acc[mt][np*2+1], ah[mt], bl + 2);
                    mma_bf16(acc[mt][np*2+0], al[mt], bh);
                    mma_bf16(acc[mt][np*2+1], al[mt], bh + 2);
                }
            }
        }
        __syncthreads();
    }

    const int g = lane >> 2, q2 = (lane & 3) * 2;
#pragma unroll
    for (int mt = 0; mt < 2; ++mt) {
        int r0 = mbase + wm*32 + mt*16 + g;
#pragma unroll
        for (int nt = 0; nt < 8; ++nt) {
            int col = nbase + wn*64 + nt*8 + q2;
            float bx = bias[col], by = bias[col+1];
            float v0x = acc[mt][nt][0] + bx, v0y = acc[mt][nt][1] + by;
            float v1x = acc[mt][nt][2] + bx, v1y = acc[mt][nt][3] + by;
            if (SPLIT) {
                uint32_t h0, l0, h1, l1;
                split2(v0x, v0y, h0, l0);
                split2(v1x, v1y, h1, l1);
                *(uint32_t*)(Ch + (size_t)r0 * Ndim + col)     = h0;
                *(uint32_t*)(Cl + (size_t)r0 * Ndim + col)     = l0;
                *(uint32_t*)(Ch + (size_t)(r0+8) * Ndim + col) = h1;
                *(uint32_t*)(Cl + (size_t)(r0+8) * Ndim + col) = l1;
            } else {
                *(float2*)(Cf + (size_t)r0 * Ndim + col)     = make_float2(v0x, v0y);
                *(float2*)(Cf + (size_t)(r0+8) * Ndim + col) = make_float2(v1x, v1y);
            }
        }
    }
}

// ---------------------------------------------------------------------------
// mma.sync causal flash attention, bf16x3. BR=128, BC=64, 256 threads (8 warps).
// Warp w owns q rows [w*16, w*16+16). Smem: Q(128rows) + K/V(64rows) hi/lo.
// ---------------------------------------------------------------------------
#define ASTB 272
#define TILE_B  (64 * ASTB)           // 17408
#define QTILE_B (128 * ASTB)          // 34816
#define ATT_SMEM (2*QTILE_B + 4*TILE_B)  // 139264

__global__ __launch_bounds__(256)
void attn_mma(const __nv_bfloat16* __restrict__ qH, const __nv_bfloat16* __restrict__ qL,
              const __nv_bfloat16* __restrict__ kvH, const __nv_bfloat16* __restrict__ kvL,
              __nv_bfloat16* __restrict__ attnH, __nv_bfloat16* __restrict__ attnL)
{
    extern __shared__ char smem[];
    const uint32_t sb = smem_u32(smem);
    const uint32_t sQH = sb, sQL = sb + QTILE_B;
    const uint32_t sKH = sb + 2*QTILE_B, sKL = sKH + TILE_B;
    const uint32_t sVH = sKL + TILE_B,   sVL = sVH + TILE_B;

    const int tid = threadIdx.x, w = tid >> 5, lane = tid & 31;
    const int q0 = blockIdx.x * 128, h = blockIdx.y, b = blockIdx.z;
    const int g = lane >> 2, qq = lane & 3;

    // ---- load Q hi/lo tile (cp.async) ----
#pragma unroll
    for (int i = 0; i < 8; ++i) {
        int lin = i*256 + tid;
        int r = lin >> 4, seg = lin & 15;
        size_t go = (size_t)(b*T_ + q0 + r) * C_ + h*D_ + seg*8;
        uint32_t so = (uint32_t)(r * ASTB + seg * 16);
        CP16(sQH + so, qH + go);
        CP16(sQL + so, qL + go);
    }
    CP_COMMIT();

    float O[16][4];
#pragma unroll
    for (int i = 0; i < 16; ++i)
#pragma unroll
        for (int j = 0; j < 4; ++j) O[i][j] = 0.f;
    float mA = -1e30f, mB = -1e30f, lA = 0.f, lB = 0.f;
    const float scale = 0.088388347648318447f;

    const uint32_t qAddr = sQH + (uint32_t)((w*16 + (lane & 15)) * ASTB + ((lane >> 4) * 8) * 2);
    const int kRowL = (lane >> 4) * 8 + (lane & 7);
    const int kColL = ((lane >> 3) & 1) * 8;
    const int vRowL = ((lane >> 3) & 1) * 8 + (lane & 7);
    const int vColL = (lane >> 4) * 8;

    const int rA = q0 + w*16 + g, rB = rA + 8;
    const int wmax = q0 + w*16 + 15;   // max q row owned by this warp

    const int ntl = q0 / 64 + 2;
    for (int t = 0; t < ntl; ++t) {
        const int t0 = t * 64;
        // ---- load K/V hi/lo tiles (cp.async) ----
#pragma unroll
        for (int i = 0; i < 4; ++i) {
            int lin = i*256 + tid;
            int r = lin >> 4, seg = lin & 15;
            size_t ko = (size_t)(b*T_ + t0 + r) * (2*C_) + h*D_ + seg*8;
            uint32_t so = (uint32_t)(r * ASTB + seg * 16);
            CP16(sKH + so, kvH + ko);
            CP16(sKL + so, kvL + ko);
            CP16(sVH + so, kvH + ko + C_);
            CP16(sVL + so, kvL + ko + C_);
        }
        CP_COMMIT();
        CP_WAIT0();
        __syncthreads();

        if (t0 <= wmax) {   // warp-uniform: skip fully-masked tiles
            // ---- S = Q K^T (bf16x3) ----
            float S[8][4];
#pragma unroll
            for (int i = 0; i < 8; ++i)
#pragma unroll
                for (int j = 0; j < 4; ++j) S[i][j] = 0.f;
#pragma unroll
            for (int ks = 0; ks < 8; ++ks) {
                uint32_t qh[4], ql[4];
                ldsm_x4(qh, qAddr + ks*32);
                ldsm_x4(ql, qAddr + (sQL - sQH) + ks*32);
#pragma unroll
                for (int grp = 0; grp < 4; ++grp) {
                    uint32_t ka = sKH + (uint32_t)((grp*16 + kRowL) * ASTB + (ks*16 + kColL) * 2);
                    uint32_t kh[4], kl[4];
                    ldsm_x4(kh, ka);
                    ldsm_x4(kl, ka + TILE_B);
                    mma_bf16(S[grp*2+0], qh, kh);
                    mma_bf16(S[grp*2+1], qh, kh + 2);
                    mma_bf16(S[grp*2+0], qh, kl);
                    mma_bf16(S[grp*2+1], qh, kl + 2);
                    mma_bf16(S[grp*2+0], ql, kh);
                    mma_bf16(S[grp*2+1], ql, kh + 2);
                }
            }

            // ---- scale + causal mask + online softmax ----
            const bool dg = (t0 + 63 > rA);
            float mtA = -1e30f, mtB = -1e30f;
#pragma unroll
            for (int nt = 0; nt < 8; ++nt) {
#pragma unroll
                for (int c = 0; c < 4; ++c) S[nt][c] *= scale;
                if (dg) {
                    int kj = t0 + nt*8 + qq*2;
                    if (kj   > rA) S[nt][0] = -1e30f;
                    if (kj+1 > rA) S[nt][1] = -1e30f;
                    if (kj   > rB) S[nt][2] = -1e30f;
                    if (kj+1 > rB) S[nt][3] = -1e30f;
                }
                mtA = fmaxf(mtA, fmaxf(S[nt][0], S[nt][1]));
                mtB = fmaxf(mtB, fmaxf(S[nt][2], S[nt][3]));
            }
            mtA = fmaxf(mtA, __shfl_xor_sync(0xffffffffu, mtA, 1));
            mtA = fmaxf(mtA, __shfl_xor_sync(0xffffffffu, mtA, 2));
            mtB = fmaxf(mtB, __shfl_xor_sync(0xffffffffu, mtB, 1));
            mtB = fmaxf(mtB, __shfl_xor_sync(0xffffffffu, mtB, 2));
            float nmA = fmaxf(mA, mtA), nmB = fmaxf(mB, mtB);
            float aA = __expf(mA - nmA), aB = __expf(mB - nmB);
            float psA = 0.f, psB = 0.f;
#pragma unroll
            for (int nt = 0; nt < 8; ++nt) {
                S[nt][0] = __expf(S[nt][0] - nmA);
                S[nt][1] = __expf(S[nt][1] - nmA);
                S[nt][2] = __expf(S[nt][2] - nmB);
                S[nt][3] = __expf(S[nt][3] - nmB);
                psA += S[nt][0] + S[nt][1];
                psB += S[nt][2] + S[nt][3];
            }
            psA += __shfl_xor_sync(0xffffffffu, psA, 1);
            psA += __shfl_xor_sync(0xffffffffu, psA, 2);
            psB += __shfl_xor_sync(0xffffffffu, psB, 1);
            psB += __shfl_xor_sync(0xffffffffu, psB, 2);
            lA = lA * aA + psA;  mA = nmA;
            lB = lB * aB + psB;  mB = nmB;
#pragma unroll
            for (int nt = 0; nt < 16; ++nt) {
                O[nt][0] *= aA; O[nt][1] *= aA;
                O[nt][2] *= aB; O[nt][3] *= aB;
            }

            // ---- O += P V (bf16x3) ----
#pragma unroll
            for (int ks = 0; ks < 4; ++ks) {
                uint32_t ah[4], al[4];
                split2(S[2*ks][0],   S[2*ks][1],   ah[0], al[0]);
                split2(S[2*ks][2],   S[2*ks][3],   ah[1], al[1]);
                split2(S[2*ks+1][0], S[2*ks+1][1], ah[2], al[2]);
                split2(S[2*ks+1][2], S[2*ks+1][3], ah[3], al[3]);
#pragma unroll
                for (int dg2 = 0; dg2 < 8; ++dg2) {
                    uint32_t va = sVH + (uint32_t)((ks*16 + vRowL) * ASTB + (dg2*16 + vColL) * 2);
                    uint32_t vh[4], vl[4];
                    ldsm_x4_t(vh, va);
                    ldsm_x4_t(vl, va + TILE_B);
                    mma_bf16(O[dg2*2+0], ah, vh);
                    mma_bf16(O[dg2*2+1], ah, vh + 2);
                    mma_bf16(O[dg2*2+0], ah, vl);
                    mma_bf16(O[dg2*2+1], ah, vl + 2);
                    mma_bf16(O[dg2*2+0], al, vh);
                    mma_bf16(O[dg2*2+1], al, vh + 2);
                }
            }
        }
        __syncthreads();
    }

    // ---- finalize ----
    const float iA = 1.f / lA, iB = 1.f / lB;
    size_t baseA = (size_t)(b*T_ + rA) * C_ + h*D_ + qq*2;
    size_t baseB = (size_t)(b*T_ + rB) * C_ + h*D_ + qq*2;
#pragma unroll
    for (int nt = 0; nt < 16; ++nt) {
        uint32_t hA, lA_, hB, lB_;
        split2(O[nt][0]*iA, O[nt][1]*iA, hA, lA_);
        split2(O[nt][2]*iB, O[nt][3]*iB, hB, lB_);
        *(uint32_t*)(attnH + baseA + nt*8) = hA;
        *(uint32_t*)(attnL + baseA + nt*8) = lA_;
        *(uint32_t*)(attnH + baseB + nt*8) = hB;
        *(uint32_t*)(attnL + baseB + nt*8) = lB_;
    }
}

// ---------------------------------------------------------------------------
extern "C" void kernel_launch(void* const* d_in, const int* in_sizes, int n_in,
                              void* d_out, int out_size)
{
    const float* enc  = (const float*)d_in[0];
    const float* dec  = (const float*)d_in[1];
    const float* W_kv = (const float*)d_in[2];
    const float* b_kv = (const float*)d_in[3];
    const float* W_q  = (const float*)d_in[4];
    const float* b_q  = (const float*)d_in[5];
    const float* W_o  = (const float*)d_in[6];
    const float* b_o  = (const float*)d_in[7];
    float* out = (float*)d_out;

    __nv_bfloat16 *encH, *encL, *decH, *decL, *kvH, *kvL, *qH, *qL, *attnH, *attnL;
    __nv_bfloat16 *WkvTH, *WkvTL, *WqTH, *WqTL, *WoTH, *WoTL;
    cudaGetSymbolAddress((void**)&encH,  g_encH);
    cudaGetSymbolAddress((void**)&encL,  g_encL);
    cudaGetSymbolAddress((void**)&decH,  g_decH);
    cudaGetSymbolAddress((void**)&decL,  g_decL);
    cudaGetSymbolAddress((void**)&kvH,   g_kvH);
    cudaGetSymbolAddress((void**)&kvL,   g_kvL);
    cudaGetSymbolAddress((void**)&qH,    g_qH);
    cudaGetSymbolAddress((void**)&qL,    g_qL);
    cudaGetSymbolAddress((void**)&attnH, g_attnH);
    cudaGetSymbolAddress((void**)&attnL, g_attnL);
    cudaGetSymbolAddress((void**)&WkvTH, g_WkvTH);
    cudaGetSymbolAddress((void**)&WkvTL, g_WkvTL);
    cudaGetSymbolAddress((void**)&WqTH,  g_WqTH);
    cudaGetSymbolAddress((void**)&WqTL,  g_WqTL);
    cudaGetSymbolAddress((void**)&WoTH,  g_WoTH);
    cudaGetSymbolAddress((void**)&WoTL,  g_WoTL);

    cudaFuncSetAttribute(gemm_bf16x3<true>,  cudaFuncAttributeMaxDynamicSharedMemorySize, GEMM_SMEM);
    cudaFuncSetAttribute(gemm_bf16x3<false>, cudaFuncAttributeMaxDynamicSharedMemorySize, GEMM_SMEM);
    cudaFuncSetAttribute(attn_mma, cudaFuncAttributeMaxDynamicSharedMemorySize, ATT_SMEM);

    const int n4 = (BT_ * C_) / 4;
    split_bf16_kernel<<<(n4 + 255) / 256, 256>>>(enc, encH, encL, n4);                       // 0
    split_bf16_kernel<<<(n4 + 255) / 256, 256>>>(dec, decH, decL, n4);                       // 1
    transpose_split_kernel<<<dim3((2*C_)/32, C_/32), dim3(32, 8)>>>(W_kv, WkvTH, WkvTL, C_, 2*C_); // 2
    gemm_bf16x3<true><<<dim3((2*C_)/128, BT_/128), 256, GEMM_SMEM>>>(encH, encL, WkvTH, WkvTL, b_kv,
                                                          nullptr, kvH, kvL, 2*C_, C_);      // 3
    transpose_split_kernel<<<dim3(C_/32, C_/32), dim3(32, 8)>>>(W_q, WqTH, WqTL, C_, C_);    // 4
    gemm_bf16x3<true><<<dim3(C_/128, BT_/128), 256, GEMM_SMEM>>>(decH, decL, WqTH, WqTL, b_q,
                                                      nullptr, qH, qL, C_, C_);              // 5
    attn_mma<<<dim3(T_/128, H_, B_), 256, ATT_SMEM>>>(qH, qL, kvH, kvL, attnH, attnL);       // 6
    transpose_split_kernel<<<dim3(C_/32, C_/32), dim3(32, 8)>>>(W_o, WoTH, WoTL, C_, C_);    // 7
    gemm_bf16x3<false><<<dim3(C_/128, BT_/128), 256, GEMM_SMEM>>>(attnH, attnL, WoTH, WoTL, b_o,
                                                       out, nullptr, nullptr, C_, C_);       // 8
}

// round 11
// speedup vs baseline: 10.7646x; 1.3295x over previous
#include <cuda_runtime.h>
#include <cuda_fp16.h>
#include <cstdint>
#include <math.h>

#define B_ 4
#define T_ 2048
#define C_ 2048
#define H_ 16
#define D_ 128
#define BT_ (B_*T_)   // 8192

// ---------------------------------------------------------------------------
// Scratch (__device__ globals, allocation-free rule)
// ---------------------------------------------------------------------------
static __device__ __half g_encH[(size_t)BT_ * C_];
static __device__ __half g_encL[(size_t)BT_ * C_];
static __device__ __half g_decH[(size_t)BT_ * C_];
static __device__ __half g_decL[(size_t)BT_ * C_];
static __device__ __half g_kvH [(size_t)BT_ * (2*C_)];
static __device__ __half g_kvL [(size_t)BT_ * (2*C_)];
static __device__ __half g_qH  [(size_t)BT_ * C_];
static __device__ __half g_qL  [(size_t)BT_ * C_];
static __device__ __half g_attnH[(size_t)BT_ * C_];
static __device__ __half g_attnL[(size_t)BT_ * C_];
static __device__ __half g_WkvT[(size_t)(2*C_) * C_];   // [4096, 2048] fp16
static __device__ __half g_WqT [(size_t)C_ * C_];
static __device__ __half g_WoT [(size_t)C_ * C_];

// ---------------------------------------------------------------------------
// PTX helpers (baseline ISA only — compute_103-safe)
// ---------------------------------------------------------------------------
__device__ __forceinline__ uint32_t smem_u32(const void* p) {
    uint32_t a;
    asm("{ .reg .u64 t; cvta.to.shared.u64 t, %1; cvt.u32.u64 %0, t; }" : "=r"(a) : "l"(p));
    return a;
}
__device__ __forceinline__ void ldsm_x4(uint32_t* r, uint32_t addr) {
    asm volatile("ldmatrix.sync.aligned.x4.m8n8.shared.b16 {%0,%1,%2,%3}, [%4];"
        : "=r"(r[0]), "=r"(r[1]), "=r"(r[2]), "=r"(r[3]) : "r"(addr));
}
__device__ __forceinline__ void ldsm_x4_t(uint32_t* r, uint32_t addr) {
    asm volatile("ldmatrix.sync.aligned.m8n8.x4.trans.shared.b16 {%0,%1,%2,%3}, [%4];"
        : "=r"(r[0]), "=r"(r[1]), "=r"(r[2]), "=r"(r[3]) : "r"(addr));
}
__device__ __forceinline__ void mma_f16(float* c, const uint32_t* a, const uint32_t* b) {
    asm volatile("mma.sync.aligned.m16n8k16.row.col.f32.f16.f16.f32 "
        "{%0,%1,%2,%3}, {%4,%5,%6,%7}, {%8,%9}, {%0,%1,%2,%3};"
        : "+f"(c[0]), "+f"(c[1]), "+f"(c[2]), "+f"(c[3])
        : "r"(a[0]), "r"(a[1]), "r"(a[2]), "r"(a[3]), "r"(b[0]), "r"(b[1]));
}
#define CP16(dst, src) \
    asm volatile("cp.async.cg.shared.global [%0], [%1], 16;" :: "r"(dst), "l"(src))
#define CP_COMMIT() asm volatile("cp.async.commit_group;" ::: "memory")
#define CP_WAIT0()  asm volatile("cp.async.wait_group 0;" ::: "memory")
#define CP_WAIT1()  asm volatile("cp.async.wait_group 1;" ::: "memory")

// fp16 hi/lo split of a float pair (packed half2 as u32)
__device__ __forceinline__ void split2h(float x, float y, uint32_t& h, uint32_t& l) {
    __half2 hb = __floats2half2_rn(x, y);
    float2 hf = __half22float2(hb);
    __half2 lb = __floats2half2_rn(x - hf.x, y - hf.y);
    h = *(uint32_t*)&hb;
    l = *(uint32_t*)&lb;
}

// ---------------------------------------------------------------------------
// Elementwise fp16 hi/lo split
// ---------------------------------------------------------------------------
__global__ __launch_bounds__(256)
void split_f16_kernel(const float* __restrict__ in, __half* __restrict__ outH,
                      __half* __restrict__ outL, int n4)
{
    int i = blockIdx.x * blockDim.x + threadIdx.x;
    if (i >= n4) return;
    float4 v = ((const float4*)in)[i];
    uint32_t h0, l0, h1, l1;
    split2h(v.x, v.y, h0, l0);
    split2h(v.z, v.w, h1, l1);
    ((uint32_t*)outH)[i*2+0] = h0; ((uint32_t*)outH)[i*2+1] = h1;
    ((uint32_t*)outL)[i*2+0] = l0; ((uint32_t*)outL)[i*2+1] = l1;
}

// ---------------------------------------------------------------------------
// Transpose to plain fp16: in [K, N] fp32 -> outT [N, K] fp16
// ---------------------------------------------------------------------------
__global__ __launch_bounds__(256)
void transpose_h_kernel(const float* __restrict__ in, __half* __restrict__ outT,
                        int K, int N)
{
    __shared__ float tile[32][33];
    int n0 = blockIdx.x * 32, k0 = blockIdx.y * 32;
    int tx = threadIdx.x, ty = threadIdx.y;
#pragma unroll
    for (int i = 0; i < 4; ++i)
        tile[ty + i*8][tx] = in[(size_t)(k0 + ty + i*8) * N + n0 + tx];
    __syncthreads();
#pragma unroll
    for (int i = 0; i < 4; ++i)
        outT[(size_t)(n0 + ty + i*8) * K + k0 + tx] = __float2half(tile[tx][ty + i*8]);
}

// ---------------------------------------------------------------------------
// fp16 2-term GEMM: C = (Ah + Al) @ BT^T + bias   (B pre-rounded to fp16)
//   3-stage cp.async ring, one __syncthreads per K-tile.
//   SPLIT=false: fp32 out;  SPLIT=true: fp16 hi/lo out.
// ---------------------------------------------------------------------------
#define KT 32
#define APAD 40
#define GT_BYTES (128 * APAD * 2)     // 10240 B per tile buffer
#define GSTAGE   (3 * GT_BYTES)       // 30720 B (Ah, Al, B)
#define GEMM_SMEM (3 * GSTAGE)        // 92160 B

template <bool SPLIT>
__global__ __launch_bounds__(256, 2)
void gemm_f16x2(const __half* __restrict__ Ah, const __half* __restrict__ Al,
                const __half* __restrict__ BT, const float* __restrict__ bias,
                float* __restrict__ Cf, __half* __restrict__ Ch, __half* __restrict__ Cl,
                int Ndim, int Kdim)
{
    extern __shared__ char gsm[];
    const uint32_t sb = smem_u32(gsm);

    const int tid  = threadIdx.x;
    const int wid  = tid >> 5, lane = tid & 31;
    const int wm   = wid >> 1;
    const int wn   = wid & 1;
    const int nbase = blockIdx.x * 128, mbase = blockIdx.y * 128;

    float acc[2][8][4];
#pragma unroll
    for (int i = 0; i < 2; ++i)
#pragma unroll
        for (int j = 0; j < 8; ++j)
#pragma unroll
            for (int k = 0; k < 4; ++k) acc[i][j][k] = 0.f;

    const int aRowL = (lane & 15), aColL = (lane >> 4) * 8;
    const int bRowL = (lane >> 4) * 8 + (lane & 7), bColL = ((lane >> 3) & 1) * 8;
    const int ldRow = tid >> 2, ldSeg = tid & 3;

    const int nkt = Kdim / KT;

    auto load_stage = [&](int kt, int s) {
        const int kofs = kt * KT;
        const uint32_t st = sb + s * GSTAGE;
#pragma unroll
        for (int half = 0; half < 2; ++half) {
            int row = ldRow + half * 64;
            size_t ga = (size_t)(mbase + row) * Kdim + kofs + ldSeg * 8;
            size_t gb = (size_t)(nbase + row) * Kdim + kofs + ldSeg * 8;
            uint32_t so = (uint32_t)(row * APAD + ldSeg * 8) * 2;
            CP16(st + 0*GT_BYTES + so, Ah + ga);
            CP16(st + 1*GT_BYTES + so, Al + ga);
            CP16(st + 2*GT_BYTES + so, BT + gb);
        }
        CP_COMMIT();
    };

    load_stage(0, 0);
    load_stage(1, 1);

    int sc = 0, sl = 2;   // compute stage, load stage
    for (int kt = 0; kt < nkt; ++kt) {
        if (kt + 1 < nkt) CP_WAIT1(); else CP_WAIT0();
        __syncthreads();
        if (kt + 2 < nkt) load_stage(kt + 2, sl);

        const uint32_t st = sb + sc * GSTAGE;
        const uint32_t aAh = st, aAl = st + GT_BYTES, aB = st + 2*GT_BYTES;

#pragma unroll
        for (int ks = 0; ks < 2; ++ks) {
            uint32_t ah[2][4], al[2][4];
#pragma unroll
            for (int mt = 0; mt < 2; ++mt) {
                uint32_t off = (uint32_t)((wm*32 + mt*16 + aRowL) * APAD + ks*16 + aColL) * 2;
                ldsm_x4(ah[mt], aAh + off);
                ldsm_x4(al[mt], aAl + off);
            }
#pragma unroll
            for (int np = 0; np < 4; ++np) {
                uint32_t boff = (uint32_t)((wn*64 + np*16 + bRowL) * APAD + ks*16 + bColL) * 2;
                uint32_t bh[4];
                ldsm_x4(bh, aB + boff);
#pragma unroll
                for (int mt = 0; mt < 2; ++mt) {
                    mma_f16(acc[mt][np*2+0], ah[mt], bh);
                    mma_f16(acc[mt][np*2+1], ah[mt], bh + 2);
                    mma_f16(acc[mt][np*2+0], al[mt], bh);
                    mma_f16(acc[mt][np*2+1], al[mt], bh + 2);
                }
            }
        }
        sc = (sc == 2) ? 0 : sc + 1;
        sl = (sl == 2) ? 0 : sl + 1;
    }

    const int g = lane >> 2, q2 = (lane & 3) * 2;
#pragma unroll
    for (int mt = 0; mt < 2; ++mt) {
        int r0 = mbase + wm*32 + mt*16 + g;
#pragma unroll
        for (int nt = 0; nt < 8; ++nt) {
            int col = nbase + wn*64 + nt*8 + q2;
            float bx = bias[col], by = bias[col+1];
            float v0x = acc[mt][nt][0] + bx, v0y = acc[mt][nt][1] + by;
            float v1x = acc[mt][nt][2] + bx, v1y = acc[mt][nt][3] + by;
            if (SPLIT) {
                uint32_t h0, l0, h1, l1;
                split2h(v0x, v0y, h0, l0);
                split2h(v1x, v1y, h1, l1);
                *(uint32_t*)(Ch + (size_t)r0 * Ndim + col)     = h0;
                *(uint32_t*)(Cl + (size_t)r0 * Ndim + col)     = l0;
                *(uint32_t*)(Ch + (size_t)(r0+8) * Ndim + col) = h1;
                *(uint32_t*)(Cl + (size_t)(r0+8) * Ndim + col) = l1;
            } else {
                *(float2*)(Cf + (size_t)r0 * Ndim + col)     = make_float2(v0x, v0y);
                *(float2*)(Cf + (size_t)(r0+8) * Ndim + col) = make_float2(v1x, v1y);
            }
        }
    }
}

// ---------------------------------------------------------------------------
// mma.sync causal flash attention, fp16 3-term, K/V double-buffered.
// BR=128, BC=64, 256 threads (8 warps). Warp w owns q rows [w*16, w*16+16).
// ---------------------------------------------------------------------------
#define ASTB 272
#define TILE_B   (64 * ASTB)            // 17408
#define QTILE_B  (128 * ASTB)           // 34816
#define KVSTAGE  (4 * TILE_B)           // 69632 (Kh, Kl, Vh, Vl)
#define ATT_SMEM (2*QTILE_B + 2*KVSTAGE)  // 208896

__global__ __launch_bounds__(256)
void attn_mma(const __half* __restrict__ qH, const __half* __restrict__ qL,
              const __half* __restrict__ kvH, const __half* __restrict__ kvL,
              __half* __restrict__ attnH, __half* __restrict__ attnL)
{
    extern __shared__ char smem[];
    const uint32_t sb = smem_u32(smem);
    const uint32_t sQH = sb;                       // + QTILE_B = sQL
    const uint32_t sKV0 = sb + 2*QTILE_B;

    const int tid = threadIdx.x, w = tid >> 5, lane = tid & 31;
    const int q0 = blockIdx.x * 128, h = blockIdx.y, b = blockIdx.z;
    const int g = lane >> 2, qq = lane & 3;

    auto load_kv = [&](int t, int s) {
        const int t0 = t * 64;
        const uint32_t st = sKV0 + s * KVSTAGE;
#pragma unroll
        for (int i = 0; i < 4; ++i) {
            int lin = i*256 + tid;
            int r = lin >> 4, seg = lin & 15;
            size_t ko = (size_t)(b*T_ + t0 + r) * (2*C_) + h*D_ + seg*8;
            uint32_t so = (uint32_t)(r * ASTB + seg * 16);
            CP16(st + 0*TILE_B + so, kvH + ko);
            CP16(st + 1*TILE_B + so, kvL + ko);
            CP16(st + 2*TILE_B + so, kvH + ko + C_);
            CP16(st + 3*TILE_B + so, kvL + ko + C_);
        }
        CP_COMMIT();
    };

    // ---- prologue: Q + KV0 (group 0), KV1 (group 1) ----
#pragma unroll
    for (int i = 0; i < 8; ++i) {
        int lin = i*256 + tid;
        int r = lin >> 4, seg = lin & 15;
        size_t go = (size_t)(b*T_ + q0 + r) * C_ + h*D_ + seg*8;
        uint32_t so = (uint32_t)(r * ASTB + seg * 16);
        CP16(sQH + so, qH + go);
        CP16(sQH + QTILE_B + so, qL + go);
    }
    load_kv(0, 0);           // Q + KV0 in one group
    load_kv(1, 1);

    float O[16][4];
#pragma unroll
    for (int i = 0; i < 16; ++i)
#pragma unroll
        for (int j = 0; j < 4; ++j) O[i][j] = 0.f;
    float mA = -1e30f, mB = -1e30f, lA = 0.f, lB = 0.f;
    const float scale = 0.088388347648318447f;

    const uint32_t qAddr = sQH + (uint32_t)((w*16 + (lane & 15)) * ASTB + ((lane >> 4) * 8) * 2);
    const int kRowL = (lane >> 4) * 8 + (lane & 7);
    const int kColL = ((lane >> 3) & 1) * 8;
    const int vRowL = ((lane >> 3) & 1) * 8 + (lane & 7);
    const int vColL = (lane >> 4) * 8;

    const int rA = q0 + w*16 + g, rB = rA + 8;
    const int wmax = q0 + w*16 + 15;

    const int ntl = q0 / 64 + 2;
    for (int t = 0; t < ntl; ++t) {
        const int t0 = t * 64;
        if (t + 1 < ntl) CP_WAIT1(); else CP_WAIT0();
        __syncthreads();

        const uint32_t sK = sKV0 + (t & 1) * KVSTAGE;
        const uint32_t sV = sK + 2*TILE_B;

        if (t0 <= wmax) {   // warp-uniform skip of fully-masked tiles
            // ---- S = Q K^T (fp16 3-term) ----
            float S[8][4];
#pragma unroll
            for (int i = 0; i < 8; ++i)
#pragma unroll
                for (int j = 0; j < 4; ++j) S[i][j] = 0.f;
#pragma unroll
            for (int ks = 0; ks < 8; ++ks) {
                uint32_t qh[4], ql[4];
                ldsm_x4(qh, qAddr + ks*32);
                ldsm_x4(ql, qAddr + QTILE_B + ks*32);
#pragma unroll
                for (int grp = 0; grp < 4; ++grp) {
                    uint32_t ka = sK + (uint32_t)((grp*16 + kRowL) * ASTB + (ks*16 + kColL) * 2);
                    uint32_t kh[4], kl[4];
                    ldsm_x4(kh, ka);
                    ldsm_x4(kl, ka + TILE_B);
                    mma_f16(S[grp*2+0], qh, kh);
                    mma_f16(S[grp*2+1], qh, kh + 2);
                    mma_f16(S[grp*2+0], qh, kl);
                    mma_f16(S[grp*2+1], qh, kl + 2);
                    mma_f16(S[grp*2+0], ql, kh);
                    mma_f16(S[grp*2+1], ql, kh + 2);
                }
            }

            // ---- scale + causal mask + online softmax ----
            const bool dg = (t0 + 63 > rA);
            float mtA = -1e30f, mtB = -1e30f;
#pragma unroll
            for (int nt = 0; nt < 8; ++nt) {
#pragma unroll
                for (int c = 0; c < 4; ++c) S[nt][c] *= scale;
                if (dg) {
                    int kj = t0 + nt*8 + qq*2;
                    if (kj   > rA) S[nt][0] = -1e30f;
                    if (kj+1 > rA) S[nt][1] = -1e30f;
                    if (kj   > rB) S[nt][2] = -1e30f;
                    if (kj+1 > rB) S[nt][3] = -1e30f;
                }
                mtA = fmaxf(mtA, fmaxf(S[nt][0], S[nt][1]));
                mtB = fmaxf(mtB, fmaxf(S[nt][2], S[nt][3]));
            }
            mtA = fmaxf(mtA, __shfl_xor_sync(0xffffffffu, mtA, 1));
            mtA = fmaxf(mtA, __shfl_xor_sync(0xffffffffu, mtA, 2));
            mtB = fmaxf(mtB, __shfl_xor_sync(0xffffffffu, mtB, 1));
            mtB = fmaxf(mtB, __shfl_xor_sync(0xffffffffu, mtB, 2));
            float nmA = fmaxf(mA, mtA), nmB = fmaxf(mB, mtB);
            float aA = __expf(mA - nmA), aB = __expf(mB - nmB);
            float psA = 0.f, psB = 0.f;
#pragma unroll
            for (int nt = 0; nt < 8; ++nt) {
                S[nt][0] = __expf(S[nt][0] - nmA);
                S[nt][1] = __expf(S[nt][1] - nmA);
                S[nt][2] = __expf(S[nt][2] - nmB);
                S[nt][3] = __expf(S[nt][3] - nmB);
                psA += S[nt][0] + S[nt][1];
                psB += S[nt][2] + S[nt][3];
            }
            psA += __shfl_xor_sync(0xffffffffu, psA, 1);
            psA += __shfl_xor_sync(0xffffffffu, psA, 2);
            psB += __shfl_xor_sync(0xffffffffu, psB, 1);
            psB += __shfl_xor_sync(0xffffffffu, psB, 2);
            lA = lA * aA + psA;  mA = nmA;
            lB = lB * aB + psB;  mB = nmB;
#pragma unroll
            for (int nt = 0; nt < 16; ++nt) {
                O[nt][0] *= aA; O[nt][1] *= aA;
                O[nt][2] *= aB; O[nt][3] *= aB;
            }

            // ---- O += P V (fp16 3-term) ----
#pragma unroll
            for (int ks = 0; ks < 4; ++ks) {
                uint32_t ph[4], pl[4];
                split2h(S[2*ks][0],   S[2*ks][1],   ph[0], pl[0]);
                split2h(S[2*ks][2],   S[2*ks][3],   ph[1], pl[1]);
                split2h(S[2*ks+1][0], S[2*ks+1][1], ph[2], pl[2]);
                split2h(S[2*ks+1][2], S[2*ks+1][3], ph[3], pl[3]);
#pragma unroll
                for (int dv = 0; dv < 8; ++dv) {
                    uint32_t va = sV + (uint32_t)((ks*16 + vRowL) * ASTB + (dv*16 + vColL) * 2);
                    uint32_t vh[4], vl[4];
                    ldsm_x4_t(vh, va);
                    ldsm_x4_t(vl, va + TILE_B);
                    mma_f16(O[dv*2+0], ph, vh);
                    mma_f16(O[dv*2+1], ph, vh + 2);
                    mma_f16(O[dv*2+0], ph, vl);
                    mma_f16(O[dv*2+1], ph, vl + 2);
                    mma_f16(O[dv*2+0], pl, vh);
                    mma_f16(O[dv*2+1], pl, vh + 2);
                }
            }
        }
        __syncthreads();
        if (t + 2 < ntl) load_kv(t + 2, t & 1);
    }

    // ---- finalize ----
    const float iA = 1.f / lA, iB = 1.f / lB;
    size_t baseA = (size_t)(b*T_ + rA) * C_ + h*D_ + qq*2;
    size_t baseB = (size_t)(b*T_ + rB) * C_ + h*D_ + qq*2;
#pragma unroll
    for (int nt = 0; nt < 16; ++nt) {
        uint32_t hA, lA_, hB, lB_;
        split2h(O[nt][0]*iA, O[nt][1]*iA, hA, lA_);
        split2h(O[nt][2]*iB, O[nt][3]*iB, hB, lB_);
        *(uint32_t*)(attnH + baseA + nt*8) = hA;
        *(uint32_t*)(attnL + baseA + nt*8) = lA_;
        *(uint32_t*)(attnH + baseB + nt*8) = hB;
        *(uint32_t*)(attnL + baseB + nt*8) = lB_;
    }
}

// ---------------------------------------------------------------------------
extern "C" void kernel_launch(void* const* d_in, const int* in_sizes, int n_in,
                              void* d_out, int out_size)
{
    const float* enc  = (const float*)d_in[0];
    const float* dec  = (const float*)d_in[1];
    const float* W_kv = (const float*)d_in[2];
    const float* b_kv = (const float*)d_in[3];
    const float* W_q  = (const float*)d_in[4];
    const float* b_q  = (const float*)d_in[5];
    const float* W_o  = (const float*)d_in[6];
    const float* b_o  = (const float*)d_in[7];
    float* out = (float*)d_out;

    __half *encH, *encL, *decH, *decL, *kvH, *kvL, *qH, *qL, *attnH, *attnL;
    __half *WkvT, *WqT, *WoT;
    cudaGetSymbolAddress((void**)&encH,  g_encH);
    cudaGetSymbolAddress((void**)&encL,  g_encL);
    cudaGetSymbolAddress((void**)&decH,  g_decH);
    cudaGetSymbolAddress((void**)&decL,  g_decL);
    cudaGetSymbolAddress((void**)&kvH,   g_kvH);
    cudaGetSymbolAddress((void**)&kvL,   g_kvL);
    cudaGetSymbolAddress((void**)&qH,    g_qH);
    cudaGetSymbolAddress((void**)&qL,    g_qL);
    cudaGetSymbolAddress((void**)&attnH, g_attnH);
    cudaGetSymbolAddress((void**)&attnL, g_attnL);
    cudaGetSymbolAddress((void**)&WkvT,  g_WkvT);
    cudaGetSymbolAddress((void**)&WqT,   g_WqT);
    cudaGetSymbolAddress((void**)&WoT,   g_WoT);

    cudaFuncSetAttribute(gemm_f16x2<true>,  cudaFuncAttributeMaxDynamicSharedMemorySize, GEMM_SMEM);
    cudaFuncSetAttribute(gemm_f16x2<false>, cudaFuncAttributeMaxDynamicSharedMemorySize, GEMM_SMEM);
    cudaFuncSetAttribute(attn_mma, cudaFuncAttributeMaxDynamicSharedMemorySize, ATT_SMEM);

    const int n4 = (BT_ * C_) / 4;
    split_f16_kernel<<<(n4 + 255) / 256, 256>>>(enc, encH, encL, n4);                         // 0
    split_f16_kernel<<<(n4 + 255) / 256, 256>>>(dec, decH, decL, n4);                         // 1
    transpose_h_kernel<<<dim3((2*C_)/32, C_/32), dim3(32, 8)>>>(W_kv, WkvT, C_, 2*C_);        // 2
    gemm_f16x2<true><<<dim3((2*C_)/128, BT_/128), 256, GEMM_SMEM>>>(encH, encL, WkvT, b_kv,
                                                        nullptr, kvH, kvL, 2*C_, C_);         // 3
    transpose_h_kernel<<<dim3(C_/32, C_/32), dim3(32, 8)>>>(W_q, WqT, C_, C_);                // 4
    gemm_f16x2<true><<<dim3(C_/128, BT_/128), 256, GEMM_SMEM>>>(decH, decL, WqT, b_q,
                                                        nullptr, qH, qL, C_, C_);             // 5
    attn_mma<<<dim3(T_/128, H_, B_), 256, ATT_SMEM>>>(qH, qL, kvH, kvL, attnH, attnL);        // 6
    transpose_h_kernel<<<dim3(C_/32, C_/32), dim3(32, 8)>>>(W_o, WoT, C_, C_);                // 7
    gemm_f16x2<false><<<dim3(C_/128, BT_/128), 256, GEMM_SMEM>>>(attnH, attnL, WoT, b_o,
                                                        out, nullptr, nullptr, C_, C_);       // 8
}